// round 1
// baseline (speedup 1.0000x reference)
#include <cuda_runtime.h>
#include <cuda_bf16.h>
#include <cstdint>

// ---------------------------------------------------------------------------
// Problem constants
// ---------------------------------------------------------------------------
#define BATCH 256
#define ENC_DIM 256
#define EMB_DIM 32
#define HEAD_HID 128
#define ACT_DIM 4

// ---------------------------------------------------------------------------
// Scratch buffers (static __device__ — no allocations allowed)
// ---------------------------------------------------------------------------
__device__ float g_conv1[(size_t)BATCH * 64 * 64 * 64];    // 268 MB
__device__ float g_conv2[(size_t)BATCH * 128 * 32 * 32];   // 134 MB
__device__ float g_v[BATCH * 256];                         // pooled vision feat

// ---------------------------------------------------------------------------
// Tiled 3x3 stride-2 pad-1 conv (NCHW, OIHW weights) + ReLU.
// Block: 256 threads, computes a 16x16 output spatial tile x 32 output
// channels for one image. Each thread: 4 spatial (along W) x 8 oc = 32 acc.
// Optional fused global-average-pool epilogue (used by conv3 where the
// 16x16 tile covers the full output image).
// ---------------------------------------------------------------------------
template <int ICTOT, int IC_CHUNK, int OCTOT, int IH, int IW, bool FUSE_POOL>
__global__ void __launch_bounds__(256)
conv3x3s2_kernel(const float* __restrict__ in, const float* __restrict__ w,
                 const float* __restrict__ bias, float* __restrict__ out)
{
    constexpr int OH = IH / 2;
    constexpr int OW = IW / 2;
    constexpr int TPD = OH / 16;            // tiles per spatial dim
    constexpr int OCB = OCTOT / 32;         // oc blocks
    constexpr int PER_IMG = OCB * TPD * TPD;

    const int bid = blockIdx.x;
    const int n = bid / PER_IMG;
    const int r = bid - n * PER_IMG;
    const int ocblk = r / (TPD * TPD);
    const int tr = r - ocblk * (TPD * TPD);
    const int ty = tr / TPD;
    const int tx = tr - ty * TPD;

    const int tid = threadIdx.x;
    const int ocg = tid >> 6;               // 0..3  (8 ocs each)
    const int sg  = tid & 63;               // spatial group
    const int ohl = sg >> 2;                // 0..15
    const int owg = sg & 3;                 // 0..3  (4 ow each)

    const int oh0 = ty * 16;
    const int ow0 = tx * 16;
    const int ih0 = oh0 * 2 - 1;
    const int iw0 = ow0 * 2 - 1;

    __shared__ float s_in[IC_CHUNK][33 * 33];
    __shared__ float s_w[32][IC_CHUNK][9];

    float acc[8][4];
#pragma unroll
    for (int o = 0; o < 8; o++)
#pragma unroll
        for (int m = 0; m < 4; m++) acc[o][m] = 0.f;

    for (int ic0 = 0; ic0 < ICTOT; ic0 += IC_CHUNK) {
        __syncthreads();   // protect previous iteration's smem readers
        // --- stage input tile (zero-padded at borders) ---
        for (int idx = tid; idx < IC_CHUNK * 1089; idx += 256) {
            int ic = idx / 1089;
            int r2 = idx - ic * 1089;
            int rr = r2 / 33;
            int cc = r2 - rr * 33;
            int gih = ih0 + rr;
            int giw = iw0 + cc;
            float v = 0.f;
            if ((unsigned)gih < (unsigned)IH && (unsigned)giw < (unsigned)IW)
                v = in[(((size_t)n * ICTOT + ic0 + ic) * IH + gih) * IW + giw];
            s_in[ic][r2] = v;
        }
        // --- stage weight slice ---
        for (int idx = tid; idx < 32 * IC_CHUNK * 9; idx += 256) {
            int o = idx / (IC_CHUNK * 9);
            int r2 = idx - o * (IC_CHUNK * 9);
            int ic = r2 / 9;
            int k = r2 - ic * 9;
            s_w[o][ic][k] = w[((size_t)(ocblk * 32 + o) * ICTOT + ic0 + ic) * 9 + k];
        }
        __syncthreads();

#pragma unroll
        for (int ic = 0; ic < IC_CHUNK; ic++) {
#pragma unroll
            for (int kh = 0; kh < 3; kh++) {
                const float* row = &s_in[ic][(ohl * 2 + kh) * 33 + owg * 8];
                float inv[9];
#pragma unroll
                for (int j = 0; j < 9; j++) inv[j] = row[j];
#pragma unroll
                for (int kw = 0; kw < 3; kw++) {
                    const float x0 = inv[kw];
                    const float x1 = inv[kw + 2];
                    const float x2 = inv[kw + 4];
                    const float x3 = inv[kw + 6];
#pragma unroll
                    for (int o = 0; o < 8; o++) {
                        const float wv = s_w[ocg * 8 + o][ic][kh * 3 + kw];
                        acc[o][0] += wv * x0;
                        acc[o][1] += wv * x1;
                        acc[o][2] += wv * x2;
                        acc[o][3] += wv * x3;
                    }
                }
            }
        }
    }

    if (!FUSE_POOL) {
#pragma unroll
        for (int o = 0; o < 8; o++) {
            const int oc = ocblk * 32 + ocg * 8 + o;
            const float bv = bias[oc];
            float4 v4;
            v4.x = fmaxf(acc[o][0] + bv, 0.f);
            v4.y = fmaxf(acc[o][1] + bv, 0.f);
            v4.z = fmaxf(acc[o][2] + bv, 0.f);
            v4.w = fmaxf(acc[o][3] + bv, 0.f);
            float* dst = &out[(((size_t)n * OCTOT + oc) * OH + oh0 + ohl) * OW
                              + ow0 + owg * 4];
            *reinterpret_cast<float4*>(dst) = v4;
        }
    } else {
        // fused ReLU + global average pool over the full 16x16 tile
        float psum[8];
#pragma unroll
        for (int o = 0; o < 8; o++) {
            const int oc = ocblk * 32 + ocg * 8 + o;
            const float bv = bias[oc];
            psum[o] = fmaxf(acc[o][0] + bv, 0.f) + fmaxf(acc[o][1] + bv, 0.f)
                    + fmaxf(acc[o][2] + bv, 0.f) + fmaxf(acc[o][3] + bv, 0.f);
        }
        __syncthreads();
        float* s_red = &s_in[0][0];   // 32 oc x 64 spatial groups = 2048 floats
#pragma unroll
        for (int o = 0; o < 8; o++) s_red[(ocg * 8 + o) * 64 + sg] = psum[o];
        __syncthreads();
        if (tid < 32) {
            float s = 0.f;
#pragma unroll 8
            for (int i = 0; i < 64; i++) s += s_red[tid * 64 + i];
            out[(size_t)n * OCTOT + ocblk * 32 + tid] = s * (1.f / 256.f);
        }
    }
}

// ---------------------------------------------------------------------------
// Fused per-sample MLP chain:
//   proprio MLP -> fusion f1,f2 -> task-emb concat -> g -> routed heads h1,h2,h3
// One block (256 threads) per sample; activations ping-pong in smem.
// ---------------------------------------------------------------------------
__global__ void __launch_bounds__(256)
mlp_chain_kernel(const float* __restrict__ v, const float* __restrict__ prop,
                 const int* __restrict__ task_ids,
                 const float* __restrict__ p1_w, const float* __restrict__ p1_b,
                 const float* __restrict__ p2_w, const float* __restrict__ p2_b,
                 const float* __restrict__ f1_w, const float* __restrict__ f1_b,
                 const float* __restrict__ f2_w, const float* __restrict__ f2_b,
                 const float* __restrict__ task_emb,
                 const float* __restrict__ g_w, const float* __restrict__ g_b,
                 const float* __restrict__ h1_w, const float* __restrict__ h1_b,
                 const float* __restrict__ h2_w, const float* __restrict__ h2_b,
                 const float* __restrict__ h3_w, const float* __restrict__ h3_b,
                 float* __restrict__ out)
{
    const int n = blockIdx.x;
    const int tid = threadIdx.x;

    __shared__ float sA[320];
    __shared__ float sB[256];
    __shared__ float sx[7];
    __shared__ float sh[64];

    sA[tid] = v[n * 256 + tid];
    if (tid < 7) sx[tid] = prop[n * 7 + tid];
    __syncthreads();

    // proprio encoder: relu(x @ p1_w + b) @ p2_w + b   (no final relu)
    if (tid < 64) {
        float a = p1_b[tid];
#pragma unroll
        for (int i = 0; i < 7; i++) a += sx[i] * p1_w[i * 64 + tid];
        sh[tid] = fmaxf(a, 0.f);
    }
    __syncthreads();
    if (tid < 64) {
        float a = p2_b[tid];
        for (int i = 0; i < 64; i++) a += sh[i] * p2_w[i * 64 + tid];
        sA[256 + tid] = a;
    }
    __syncthreads();

    // f1: 320 -> 256, relu
    {
        float a = f1_b[tid];
        for (int i = 0; i < 320; i++) a += sA[i] * f1_w[i * 256 + tid];
        sB[tid] = fmaxf(a, 0.f);
    }
    __syncthreads();
    // f2: 256 -> 256, relu -> sA[0..255]
    {
        float a = f2_b[tid];
        for (int i = 0; i < 256; i++) a += sB[i] * f2_w[i * 256 + tid];
        sA[tid] = fmaxf(a, 0.f);
    }
    const int t = task_ids[n];
    if (tid < 32) sA[256 + tid] = task_emb[t * 32 + tid];
    __syncthreads();

    // g: 288 -> 256, relu -> sB
    {
        float a = g_b[tid];
        for (int i = 0; i < 288; i++) a += sA[i] * g_w[i * 256 + tid];
        sB[tid] = fmaxf(a, 0.f);
    }
    __syncthreads();

    // routed head 1: 256 -> 128, relu
    const float* w1 = h1_w + (size_t)t * ENC_DIM * HEAD_HID;
    if (tid < 128) {
        float a = h1_b[t * HEAD_HID + tid];
        for (int i = 0; i < 256; i++) a += sB[i] * w1[i * 128 + tid];
        sA[tid] = fmaxf(a, 0.f);
    }
    __syncthreads();
    // routed head 2: 128 -> 128, relu
    const float* w2 = h2_w + (size_t)t * HEAD_HID * HEAD_HID;
    if (tid < 128) {
        float a = h2_b[t * HEAD_HID + tid];
        for (int i = 0; i < 128; i++) a += sA[i] * w2[i * 128 + tid];
        sB[tid] = fmaxf(a, 0.f);
    }
    __syncthreads();
    // routed head 3: 128 -> 4 (no relu)
    const float* w3 = h3_w + (size_t)t * HEAD_HID * ACT_DIM;
    if (tid < 4) {
        float a = h3_b[t * ACT_DIM + tid];
        for (int i = 0; i < 128; i++) a += sB[i] * w3[i * 4 + tid];
        out[n * 4 + tid] = a;
    }
}

// ---------------------------------------------------------------------------
// kernel_launch
// ---------------------------------------------------------------------------
extern "C" void kernel_launch(void* const* d_in, const int* in_sizes, int n_in,
                              void* d_out, int out_size)
{
    const float* images = (const float*)d_in[0];
    const float* prop   = (const float*)d_in[1];
    const int*   tids   = (const int*)d_in[2];
    const float* c1_w = (const float*)d_in[3];
    const float* c1_b = (const float*)d_in[4];
    const float* c2_w = (const float*)d_in[5];
    const float* c2_b = (const float*)d_in[6];
    const float* c3_w = (const float*)d_in[7];
    const float* c3_b = (const float*)d_in[8];
    const float* p1_w = (const float*)d_in[9];
    const float* p1_b = (const float*)d_in[10];
    const float* p2_w = (const float*)d_in[11];
    const float* p2_b = (const float*)d_in[12];
    const float* f1_w = (const float*)d_in[13];
    const float* f1_b = (const float*)d_in[14];
    const float* f2_w = (const float*)d_in[15];
    const float* f2_b = (const float*)d_in[16];
    const float* temb = (const float*)d_in[17];
    const float* g_w  = (const float*)d_in[18];
    const float* g_b  = (const float*)d_in[19];
    const float* h1_w = (const float*)d_in[20];
    const float* h1_b = (const float*)d_in[21];
    const float* h2_w = (const float*)d_in[22];
    const float* h2_b = (const float*)d_in[23];
    const float* h3_w = (const float*)d_in[24];
    const float* h3_b = (const float*)d_in[25];
    float* out = (float*)d_out;

    float* conv1_out;
    float* conv2_out;
    float* v_out;
    cudaGetSymbolAddress((void**)&conv1_out, g_conv1);
    cudaGetSymbolAddress((void**)&conv2_out, g_conv2);
    cudaGetSymbolAddress((void**)&v_out, g_v);

    // conv1: [256,3,128,128] -> [256,64,64,64]
    conv3x3s2_kernel<3, 3, 64, 128, 128, false>
        <<<BATCH * 2 * 16, 256>>>(images, c1_w, c1_b, conv1_out);
    // conv2: -> [256,128,32,32]
    conv3x3s2_kernel<64, 8, 128, 64, 64, false>
        <<<BATCH * 4 * 4, 256>>>(conv1_out, c2_w, c2_b, conv2_out);
    // conv3 + fused global avg pool: -> v[256,256]
    conv3x3s2_kernel<128, 8, 256, 32, 32, true>
        <<<BATCH * 8, 256>>>(conv2_out, c3_w, c3_b, v_out);

    // fused MLP chain + routed heads -> out[256,4]
    mlp_chain_kernel<<<BATCH, 256>>>(
        v_out, prop, tids,
        p1_w, p1_b, p2_w, p2_b,
        f1_w, f1_b, f2_w, f2_b,
        temb, g_w, g_b,
        h1_w, h1_b, h2_w, h2_b, h3_w, h3_b,
        out);
}

// round 2
// speedup vs baseline: 1.5920x; 1.5920x over previous
#include <cuda_runtime.h>
#include <cuda_bf16.h>
#include <cstdint>

#define BATCH 256
#define ENC_DIM 256
#define EMB_DIM 32
#define HEAD_HID 128
#define ACT_DIM 4

// ---------------------------------------------------------------------------
// Scratch (static __device__ — no allocations allowed)
// ---------------------------------------------------------------------------
__device__ float g_conv1[(size_t)BATCH * 64 * 64 * 64];    // 268 MB
__device__ float g_conv2[(size_t)BATCH * 128 * 32 * 32];   // 134 MB
__device__ float g_vpart[(size_t)BATCH * 2 * 256];         // conv3 pool partials

__device__ __forceinline__ uint32_t f2tf32(float f) {
    uint32_t r;
    asm("cvt.rna.tf32.f32 %0, %1;" : "=r"(r) : "f"(f));
    return r;
}

__device__ __forceinline__ void mma_tf32(float c[4], uint32_t a0, uint32_t a1,
                                         uint32_t a2, uint32_t a3,
                                         uint32_t b0, uint32_t b1) {
    asm volatile(
        "mma.sync.aligned.m16n8k8.row.col.f32.tf32.tf32.f32 "
        "{%0,%1,%2,%3}, {%4,%5,%6,%7}, {%8,%9}, {%0,%1,%2,%3};"
        : "+f"(c[0]), "+f"(c[1]), "+f"(c[2]), "+f"(c[3])
        : "r"(a0), "r"(a1), "r"(a2), "r"(a3), "r"(b0), "r"(b1));
}

// ---------------------------------------------------------------------------
// Implicit-GEMM 3x3 stride-2 pad-1 conv (NCHW in, OIHW w) + ReLU via tf32 mma.
// Block = 256 threads (8 warps). Output tile: M=128 spatial (OH_TILE rows x
// full OW) x N=64 output channels. K = ic*9, chunked by IC_CHUNK channels.
// warp w computes rows [16w, 16w+16). A-fragments gathered from the raw
// input tile via a k->offset table (fused im2col). FUSE_POOL: ReLU + partial
// global-avg-pool reduced deterministically into g_vpart.
// ---------------------------------------------------------------------------
template <int ICTOT, int IC_CHUNK, int OCTOT, int IH, int IW, int OH_TILE, bool FUSE_POOL>
__global__ void __launch_bounds__(256)
conv_mma_kernel(const float* __restrict__ in, const float* __restrict__ w,
                const float* __restrict__ bias, float* __restrict__ out)
{
    constexpr int OH = IH / 2;
    constexpr int OW = IW / 2;
    constexpr int LOG_OW = (OW == 64) ? 6 : (OW == 32) ? 5 : 4;
    constexpr int IN_ROWS = 2 * OH_TILE + 1;
    constexpr int IN_COLS = 2 * OW + 1;
    constexpr int RC = IN_ROWS * IN_COLS;
    constexpr int KC = IC_CHUNK * 9;
    constexpr int KC_PAD = (KC + 7) & ~7;
    constexpr int NSTEP = KC_PAD / 8;
    constexpr bool PADDED = (KC_PAD != KC);
    constexpr int MBLK = OH / OH_TILE;
    constexpr int NBLK = OCTOT / 64;
    constexpr int WSTR = 68;   // padded n-stride for s_w rows

    __shared__ float s_in[IC_CHUNK * RC];
    __shared__ alignas(16) float s_w[KC_PAD * WSTR];
    __shared__ int s_ktab[KC_PAD];

    const int bid = blockIdx.x;
    const int n = bid / (MBLK * NBLK);
    const int r = bid - n * (MBLK * NBLK);
    const int mblk = r / NBLK;
    const int nblk = r - mblk * NBLK;
    const int oh0 = mblk * OH_TILE;

    const int tid = threadIdx.x;
    const int warp = tid >> 5;
    const int lane = tid & 31;
    const int lm4 = lane & 3;
    const int lg4 = lane >> 2;
    const int goff = lg4 * 8;

    const int row0 = warp * 16 + lg4;
    const int row1 = row0 + 8;
    const int rb0 = ((row0 >> LOG_OW) * 2) * IN_COLS + (row0 & (OW - 1)) * 2;
    const int rb1 = ((row1 >> LOG_OW) * 2) * IN_COLS + (row1 & (OW - 1)) * 2;

    // k -> input-tile offset table (chunk-invariant)
    if (tid < KC_PAD) {
        int v = -1;
        if (tid < KC) {
            int ic = tid / 9, q = tid - ic * 9;
            v = ic * RC + (q / 3) * IN_COLS + (q % 3);
        }
        s_ktab[tid] = v;
    }
    // zero padded B rows (written once, never overwritten)
    if (PADDED) {
        for (int idx = tid; idx < 64 * (KC_PAD - KC); idx += 256) {
            int k = KC + (idx >> 6);
            s_w[k * WSTR + (idx & 63)] = 0.f;
        }
    }

    float acc[8][4];
#pragma unroll
    for (int t = 0; t < 8; t++)
#pragma unroll
        for (int m = 0; m < 4; m++) acc[t][m] = 0.f;

    for (int ic0 = 0; ic0 < ICTOT; ic0 += IC_CHUNK) {
        __syncthreads();
        // --- stage input tile (zero-padded at borders), tf32-rounded ---
        for (int idx = tid; idx < IC_CHUNK * RC; idx += 256) {
            int ic = idx / RC;
            int r2 = idx - ic * RC;
            int rr = r2 / IN_COLS;
            int cc = r2 - rr * IN_COLS;
            int gih = oh0 * 2 - 1 + rr;
            int giw = cc - 1;
            float v = 0.f;
            if ((unsigned)gih < (unsigned)IH && (unsigned)giw < (unsigned)IW)
                v = in[(((size_t)n * ICTOT + ic0 + ic) * IH + gih) * IW + giw];
            s_in[idx] = __uint_as_float(f2tf32(v));
        }
        // --- stage weight slice [KC x 64], permuted so each thread's 8
        //     n-tiles are contiguous: col' = (n&7)*8 + (n>>3) ---
        for (int idx = tid; idx < 64 * KC; idx += 256) {
            int nn = idx / KC;
            int k = idx - nn * KC;
            int ic = k / 9, q = k - ic * 9;
            float v = w[((size_t)(nblk * 64 + nn) * ICTOT + ic0 + ic) * 9 + q];
            s_w[k * WSTR + ((nn & 7) << 3) + (nn >> 3)] = __uint_as_float(f2tf32(v));
        }
        __syncthreads();

#pragma unroll
        for (int ks = 0; ks < NSTEP; ks++) {
            const int c0 = (ks << 3) + lm4;
            const int c1 = c0 + 4;
            const int kb0 = s_ktab[c0];
            const int kb1 = s_ktab[c1];
            uint32_t a0, a1, a2, a3;
            if (PADDED) {
                a0 = kb0 >= 0 ? __float_as_uint(s_in[rb0 + kb0]) : 0u;
                a1 = kb0 >= 0 ? __float_as_uint(s_in[rb1 + kb0]) : 0u;
                a2 = kb1 >= 0 ? __float_as_uint(s_in[rb0 + kb1]) : 0u;
                a3 = kb1 >= 0 ? __float_as_uint(s_in[rb1 + kb1]) : 0u;
            } else {
                a0 = __float_as_uint(s_in[rb0 + kb0]);
                a1 = __float_as_uint(s_in[rb1 + kb0]);
                a2 = __float_as_uint(s_in[rb0 + kb1]);
                a3 = __float_as_uint(s_in[rb1 + kb1]);
            }
            const float4 b0lo = *(const float4*)&s_w[c0 * WSTR + goff];
            const float4 b0hi = *(const float4*)&s_w[c0 * WSTR + goff + 4];
            const float4 b1lo = *(const float4*)&s_w[c1 * WSTR + goff];
            const float4 b1hi = *(const float4*)&s_w[c1 * WSTR + goff + 4];
            const uint32_t* u0lo = (const uint32_t*)&b0lo;
            const uint32_t* u0hi = (const uint32_t*)&b0hi;
            const uint32_t* u1lo = (const uint32_t*)&b1lo;
            const uint32_t* u1hi = (const uint32_t*)&b1hi;
#pragma unroll
            for (int t = 0; t < 4; t++)
                mma_tf32(acc[t], a0, a1, a2, a3, u0lo[t], u1lo[t]);
#pragma unroll
            for (int t = 0; t < 4; t++)
                mma_tf32(acc[4 + t], a0, a1, a2, a3, u0hi[t], u1hi[t]);
        }
    }

    const int col0 = 2 * lm4;

    if (!FUSE_POOL) {
        const int r0oh = oh0 + (row0 >> LOG_OW), r0ow = row0 & (OW - 1);
        const int r1oh = oh0 + (row1 >> LOG_OW), r1ow = row1 & (OW - 1);
#pragma unroll
        for (int t = 0; t < 8; t++) {
            const int oc0 = nblk * 64 + t * 8 + col0;
            const float bv0 = bias[oc0];
            const float bv1 = bias[oc0 + 1];
            float* o0 = out + ((size_t)n * OCTOT + oc0) * (OH * OW);
            float* o1 = out + ((size_t)n * OCTOT + oc0 + 1) * (OH * OW);
            o0[r0oh * OW + r0ow] = fmaxf(acc[t][0] + bv0, 0.f);
            o1[r0oh * OW + r0ow] = fmaxf(acc[t][1] + bv1, 0.f);
            o0[r1oh * OW + r1ow] = fmaxf(acc[t][2] + bv0, 0.f);
            o1[r1oh * OW + r1ow] = fmaxf(acc[t][3] + bv1, 0.f);
        }
    } else {
        // ReLU + partial global-avg-pool over this block's 128 spatial rows.
        __shared__ float s_red[8 * 64];
#pragma unroll
        for (int t = 0; t < 8; t++) {
            const int oc0 = nblk * 64 + t * 8 + col0;
            const float bv0 = bias[oc0];
            const float bv1 = bias[oc0 + 1];
            float s0 = fmaxf(acc[t][0] + bv0, 0.f) + fmaxf(acc[t][2] + bv0, 0.f);
            float s1 = fmaxf(acc[t][1] + bv1, 0.f) + fmaxf(acc[t][3] + bv1, 0.f);
#pragma unroll
            for (int d = 4; d < 32; d <<= 1) {
                s0 += __shfl_down_sync(0xffffffffu, s0, d);
                s1 += __shfl_down_sync(0xffffffffu, s1, d);
            }
            if (lane < 4) {
                s_red[warp * 64 + t * 8 + col0] = s0;
                s_red[warp * 64 + t * 8 + col0 + 1] = s1;
            }
        }
        __syncthreads();
        if (tid < 64) {
            float s = 0.f;
#pragma unroll
            for (int i = 0; i < 8; i++) s += s_red[i * 64 + tid];
            out[((size_t)n * MBLK + mblk) * 256 + nblk * 64 + tid] = s;
        }
    }
}

// ---------------------------------------------------------------------------
// Fused per-sample MLP chain (combines pool partials first).
// ---------------------------------------------------------------------------
__global__ void __launch_bounds__(256)
mlp_chain_kernel(const float* __restrict__ vpart, const float* __restrict__ prop,
                 const int* __restrict__ task_ids,
                 const float* __restrict__ p1_w, const float* __restrict__ p1_b,
                 const float* __restrict__ p2_w, const float* __restrict__ p2_b,
                 const float* __restrict__ f1_w, const float* __restrict__ f1_b,
                 const float* __restrict__ f2_w, const float* __restrict__ f2_b,
                 const float* __restrict__ task_emb,
                 const float* __restrict__ g_w, const float* __restrict__ g_b,
                 const float* __restrict__ h1_w, const float* __restrict__ h1_b,
                 const float* __restrict__ h2_w, const float* __restrict__ h2_b,
                 const float* __restrict__ h3_w, const float* __restrict__ h3_b,
                 float* __restrict__ out)
{
    const int n = blockIdx.x;
    const int tid = threadIdx.x;

    __shared__ float sA[320];
    __shared__ float sB[256];
    __shared__ float sx[7];
    __shared__ float sh[64];

    sA[tid] = (vpart[((size_t)n * 2 + 0) * 256 + tid] +
               vpart[((size_t)n * 2 + 1) * 256 + tid]) * (1.f / 256.f);
    if (tid < 7) sx[tid] = prop[n * 7 + tid];
    __syncthreads();

    if (tid < 64) {
        float a = p1_b[tid];
#pragma unroll
        for (int i = 0; i < 7; i++) a += sx[i] * p1_w[i * 64 + tid];
        sh[tid] = fmaxf(a, 0.f);
    }
    __syncthreads();
    if (tid < 64) {
        float a = p2_b[tid];
        for (int i = 0; i < 64; i++) a += sh[i] * p2_w[i * 64 + tid];
        sA[256 + tid] = a;
    }
    __syncthreads();

    {
        float a = f1_b[tid];
        for (int i = 0; i < 320; i++) a += sA[i] * f1_w[i * 256 + tid];
        sB[tid] = fmaxf(a, 0.f);
    }
    __syncthreads();
    {
        float a = f2_b[tid];
        for (int i = 0; i < 256; i++) a += sB[i] * f2_w[i * 256 + tid];
        sA[tid] = fmaxf(a, 0.f);
    }
    const int t = task_ids[n];
    if (tid < 32) sA[256 + tid] = task_emb[t * 32 + tid];
    __syncthreads();

    {
        float a = g_b[tid];
        for (int i = 0; i < 288; i++) a += sA[i] * g_w[i * 256 + tid];
        sB[tid] = fmaxf(a, 0.f);
    }
    __syncthreads();

    const float* w1 = h1_w + (size_t)t * ENC_DIM * HEAD_HID;
    if (tid < 128) {
        float a = h1_b[t * HEAD_HID + tid];
        for (int i = 0; i < 256; i++) a += sB[i] * w1[i * 128 + tid];
        sA[tid] = fmaxf(a, 0.f);
    }
    __syncthreads();
    const float* w2 = h2_w + (size_t)t * HEAD_HID * HEAD_HID;
    if (tid < 128) {
        float a = h2_b[t * HEAD_HID + tid];
        for (int i = 0; i < 128; i++) a += sA[i] * w2[i * 128 + tid];
        sB[tid] = fmaxf(a, 0.f);
    }
    __syncthreads();
    const float* w3 = h3_w + (size_t)t * HEAD_HID * ACT_DIM;
    if (tid < 4) {
        float a = h3_b[t * ACT_DIM + tid];
        for (int i = 0; i < 128; i++) a += sB[i] * w3[i * 4 + tid];
        out[n * 4 + tid] = a;
    }
}

// ---------------------------------------------------------------------------
extern "C" void kernel_launch(void* const* d_in, const int* in_sizes, int n_in,
                              void* d_out, int out_size)
{
    const float* images = (const float*)d_in[0];
    const float* prop   = (const float*)d_in[1];
    const int*   tids   = (const int*)d_in[2];
    const float* c1_w = (const float*)d_in[3];
    const float* c1_b = (const float*)d_in[4];
    const float* c2_w = (const float*)d_in[5];
    const float* c2_b = (const float*)d_in[6];
    const float* c3_w = (const float*)d_in[7];
    const float* c3_b = (const float*)d_in[8];
    const float* p1_w = (const float*)d_in[9];
    const float* p1_b = (const float*)d_in[10];
    const float* p2_w = (const float*)d_in[11];
    const float* p2_b = (const float*)d_in[12];
    const float* f1_w = (const float*)d_in[13];
    const float* f1_b = (const float*)d_in[14];
    const float* f2_w = (const float*)d_in[15];
    const float* f2_b = (const float*)d_in[16];
    const float* temb = (const float*)d_in[17];
    const float* g_w  = (const float*)d_in[18];
    const float* g_b  = (const float*)d_in[19];
    const float* h1_w = (const float*)d_in[20];
    const float* h1_b = (const float*)d_in[21];
    const float* h2_w = (const float*)d_in[22];
    const float* h2_b = (const float*)d_in[23];
    const float* h3_w = (const float*)d_in[24];
    const float* h3_b = (const float*)d_in[25];
    float* out = (float*)d_out;

    float *conv1_out, *conv2_out, *vpart;
    cudaGetSymbolAddress((void**)&conv1_out, g_conv1);
    cudaGetSymbolAddress((void**)&conv2_out, g_conv2);
    cudaGetSymbolAddress((void**)&vpart, g_vpart);

    // conv1: [256,3,128,128] -> [256,64,64,64]   (M tiles: 64/2=32, N: 1)
    conv_mma_kernel<3, 3, 64, 128, 128, 2, false>
        <<<BATCH * 32 * 1, 256>>>(images, c1_w, c1_b, conv1_out);
    // conv2: -> [256,128,32,32]                  (M tiles: 8, N: 2)
    conv_mma_kernel<64, 8, 128, 64, 64, 4, false>
        <<<BATCH * 8 * 2, 256>>>(conv1_out, c2_w, c2_b, conv2_out);
    // conv3 + fused pool partials -> g_vpart     (M tiles: 2, N: 4)
    conv_mma_kernel<128, 8, 256, 32, 32, 8, true>
        <<<BATCH * 2 * 4, 256>>>(conv2_out, c3_w, c3_b, vpart);

    mlp_chain_kernel<<<BATCH, 256>>>(
        vpart, prop, tids,
        p1_w, p1_b, p2_w, p2_b,
        f1_w, f1_b, f2_w, f2_b,
        temb, g_w, g_b,
        h1_w, h1_b, h2_w, h2_b, h3_w, h3_b,
        out);
}

// round 4
// speedup vs baseline: 1.7540x; 1.1018x over previous
#include <cuda_runtime.h>
#include <cuda_fp16.h>
#include <cstdint>

#define BATCH 256
#define ENC_DIM 256
#define EMB_DIM 32
#define HEAD_HID 128
#define ACT_DIM 4

// ---------------------------------------------------------------------------
// Scratch (static __device__ — no allocations allowed)
// ---------------------------------------------------------------------------
__device__ float g_conv1[(size_t)BATCH * 64 * 64 * 64];
__device__ float g_conv2[(size_t)BATCH * 128 * 32 * 32];
__device__ float g_vpart[(size_t)BATCH * 2 * 256];

// ---------------------------------------------------------------------------
// smem byte offsets (dynamic smem)
// ---------------------------------------------------------------------------
#define OFF_BIAS  0
#define OFF_KTAB  256
#define OFF_A0    1024
#define OFF_A1    17408
#define OFF_B0    33792
#define OFF_B1    41984
#define OFF_RAW   50176

__device__ __forceinline__ uint32_t smem_u32(const void* p) {
    uint32_t a;
    asm("{ .reg .u64 t; cvta.to.shared.u64 t, %1; cvt.u32.u64 %0, t; }"
        : "=r"(a) : "l"(p));
    return a;
}
__device__ __forceinline__ uint32_t swz(uint32_t off) {
    return off ^ ((off >> 3) & 0x70);
}
__device__ __forceinline__ void ldm_x4(uint32_t r[4], uint32_t addr) {
    asm volatile("ldmatrix.sync.aligned.m8n8.x4.shared.b16 {%0,%1,%2,%3}, [%4];"
                 : "=r"(r[0]), "=r"(r[1]), "=r"(r[2]), "=r"(r[3]) : "r"(addr));
}
__device__ __forceinline__ void mma_f16(float c[4], const uint32_t a[4],
                                        uint32_t b0, uint32_t b1) {
    asm volatile(
        "mma.sync.aligned.m16n8k16.row.col.f32.f16.f16.f32 "
        "{%0,%1,%2,%3},{%4,%5,%6,%7},{%8,%9},{%0,%1,%2,%3};"
        : "+f"(c[0]), "+f"(c[1]), "+f"(c[2]), "+f"(c[3])
        : "r"(a[0]), "r"(a[1]), "r"(a[2]), "r"(a[3]), "r"(b0), "r"(b1));
}
__device__ __forceinline__ uint32_t pack2(unsigned short lo, unsigned short hi) {
    return (uint32_t)lo | ((uint32_t)hi << 16);
}

// ---------------------------------------------------------------------------
// fp16 mma implicit-GEMM conv 3x3 s2 p1 (NCHW, OIHW) + ReLU (+ optional pool).
// Block 256 thr (8 warps, 4Mx2N). Block tile M=128 spatial x N=64 oc.
// K = ICTOT*9 in chunks of 64 halves (=128B SW128 rows), double-buffered,
// staging software-pipelined behind the mma stream.
// ---------------------------------------------------------------------------
template <int ICTOT, int OCTOT, int IH, int IW, int OH_TILE, int RAW_ICS, bool FUSE_POOL>
__global__ void __launch_bounds__(256)
conv_hmma_kernel(const float* __restrict__ in, const float* __restrict__ w,
                 const float* __restrict__ bias, float* __restrict__ out)
{
    constexpr int OH = IH / 2;
    constexpr int OW = IW / 2;
    constexpr int LOG_OW = (OW == 64) ? 6 : (OW == 32) ? 5 : 4;
    constexpr int KTOT = ICTOT * 9;
    constexpr int NCH = (KTOT + 63) / 64;
    constexpr int IN_COLS = 2 * OW + 1;
    constexpr int IN_ROWS = 2 * OH_TILE + 1;
    constexpr int RC = IN_ROWS * IN_COLS;
    constexpr int RAW_MAX = RAW_ICS * RC;
    constexpr int NRV = (RAW_MAX + 255) / 256;
    constexpr int MBLK = OH / OH_TILE;
    constexpr int NBLK = OCTOT / 64;

    extern __shared__ char smem[];
    const uint32_t sb = smem_u32(smem);
    float* s_bias = (float*)(smem + OFF_BIAS);
    int* ktab = (int*)(smem + OFF_KTAB);
    __half* raw = (__half*)(smem + OFF_RAW);

    const int bid = blockIdx.x;
    const int n = bid / (MBLK * NBLK);
    const int r = bid - n * (MBLK * NBLK);
    const int mblk = r / NBLK;
    const int nblk = r - mblk * NBLK;
    const int oh0 = mblk * OH_TILE;

    const int tid = threadIdx.x;
    const int warp = tid >> 5;
    const int lane = tid & 31;
    const int mwarp = warp >> 1;
    const int nwarp = warp & 1;

    if (tid < 64) s_bias[tid] = bias[nblk * 64 + tid];

    // A-build mapping: row am = tid>>1, halves segment (tid&1)*32
    const int am = tid >> 1;
    const int arb = ((am >> LOG_OW) * 2) * IN_COLS + (am & (OW - 1)) * 2;
    const int ahb = (tid & 1) * 32;
    // B mapping: row n = tid>>2, segment (tid&3)*16 halves
    const int bn = tid >> 2;
    const int bseg = (tid & 3) * 16;
    const float* wrow = w + (size_t)(nblk * 64 + bn) * KTOT;

    unsigned short rv[NRV];
    unsigned short bv[16];

    // ---- staging helpers ----
    auto load_raw = [&](int cn) {
        const int ic0 = (cn * 64) / 9;
        const int ics = (RAW_ICS < ICTOT - ic0) ? RAW_ICS : (ICTOT - ic0);
        const int lim = ics * RC;
#pragma unroll
        for (int i = 0; i < NRV; i++) {
            int idx = i * 256 + tid;
            float v = 0.f;
            if (idx < lim) {
                int ic = idx / RC;
                int r2 = idx - ic * RC;
                int rr = r2 / IN_COLS;
                int cc = r2 - rr * IN_COLS;
                int gih = oh0 * 2 - 1 + rr;
                int giw = cc - 1;
                if ((unsigned)gih < (unsigned)IH && (unsigned)giw < (unsigned)IW)
                    v = in[((size_t)n * ICTOT + ic0 + ic) * (IH * IW) + gih * IW + giw];
            }
            rv[i] = __half_as_ushort(__float2half_rn(v));
        }
    };
    auto load_B = [&](int cn) {
        const int kb = cn * 64 + bseg;
#pragma unroll
        for (int j = 0; j < 16; j++) {
            float v = (kb + j < KTOT) ? wrow[kb + j] : 0.f;
            bv[j] = __half_as_ushort(__float2half_rn(v));
        }
    };
    auto sts_raw_ktab = [&](int cn) {
#pragma unroll
        for (int i = 0; i < NRV; i++) {
            int idx = i * 256 + tid;
            if (idx < RAW_MAX) raw[idx] = __ushort_as_half(rv[i]);
        }
        if (tid < 64) {
            int kk = cn * 64 + tid;
            int v = -1;
            if (kk < KTOT) {
                int ic = kk / 9, q = kk - ic * 9;
                v = (ic - (cn * 64) / 9) * RC + (q / 3) * IN_COLS + (q % 3);
            }
            ktab[tid] = v;
        }
    };
    auto build_A = [&](uint32_t abase) {
        char* dst = smem + abase;
#pragma unroll
        for (int g = 0; g < 4; g++) {
            const int kb = ahb + g * 8;
            unsigned short h[8];
#pragma unroll
            for (int j = 0; j < 8; j++) {
                int t = ktab[kb + j];
                h[j] = (t >= 0) ? __half_as_ushort(raw[arb + t]) : (unsigned short)0;
            }
            uint4 q;
            q.x = pack2(h[0], h[1]); q.y = pack2(h[2], h[3]);
            q.z = pack2(h[4], h[5]); q.w = pack2(h[6], h[7]);
            *(uint4*)(dst + swz((uint32_t)(am * 128 + kb * 2))) = q;
        }
    };
    auto sts_B = [&](uint32_t bbase) {
        char* dst = smem + bbase;
#pragma unroll
        for (int g = 0; g < 2; g++) {
            uint4 q;
            q.x = pack2(bv[g * 8 + 0], bv[g * 8 + 1]);
            q.y = pack2(bv[g * 8 + 2], bv[g * 8 + 3]);
            q.z = pack2(bv[g * 8 + 4], bv[g * 8 + 5]);
            q.w = pack2(bv[g * 8 + 6], bv[g * 8 + 7]);
            *(uint4*)(dst + swz((uint32_t)(bn * 128 + (bseg + g * 8) * 2))) = q;
        }
    };

    float acc[2][4][4];
#pragma unroll
    for (int mt = 0; mt < 2; mt++)
#pragma unroll
        for (int nt = 0; nt < 4; nt++)
#pragma unroll
            for (int i = 0; i < 4; i++) acc[mt][nt][i] = 0.f;

    auto do_mma = [&](uint32_t abase, uint32_t bbase) {
#pragma unroll
        for (int ks = 0; ks < 4; ks++) {
            const uint32_t colb = ks * 32 + ((lane >> 4) << 4);
            uint32_t a[2][4], bf[2][4];
#pragma unroll
            for (int mt = 0; mt < 2; mt++) {
                const uint32_t row = mwarp * 32 + mt * 16 + (lane & 15);
                ldm_x4(a[mt], sb + abase + swz(row * 128 + colb));
            }
#pragma unroll
            for (int np = 0; np < 2; np++) {
                const uint32_t row = nwarp * 32 + np * 16 + (lane & 15);
                ldm_x4(bf[np], sb + bbase + swz(row * 128 + colb));
            }
#pragma unroll
            for (int mt = 0; mt < 2; mt++)
#pragma unroll
                for (int nt = 0; nt < 4; nt++)
                    mma_f16(acc[mt][nt], a[mt], bf[nt >> 1][nt & 1],
                            bf[nt >> 1][2 + (nt & 1)]);
        }
    };

    // ---- prologue: stage chunk 0 ----
    load_raw(0);
    load_B(0);
    sts_raw_ktab(0);
    __syncthreads();
    build_A(OFF_A0);
    sts_B(OFF_B0);
    __syncthreads();

    // ---- main loop: pipelined ----
    for (int c = 0; c < NCH; c++) {
        const bool more = (c + 1 < NCH);
        if (more) { load_raw(c + 1); load_B(c + 1); }
        do_mma((c & 1) ? OFF_A1 : OFF_A0, (c & 1) ? OFF_B1 : OFF_B0);
        if (more) sts_raw_ktab(c + 1);
        __syncthreads();
        if (more) {
            build_A(((c + 1) & 1) ? OFF_A1 : OFF_A0);
            sts_B(((c + 1) & 1) ? OFF_B1 : OFF_B0);
        }
        __syncthreads();
    }

    // ---- epilogue ----
    if (!FUSE_POOL) {
        // transpose through smem -> coalesced float4 global stores
        float* sE = (float*)(smem + OFF_A0);   // [64 oc][132 stride] floats
#pragma unroll
        for (int mt = 0; mt < 2; mt++) {
            const int r0 = mwarp * 32 + mt * 16 + (lane >> 2);
#pragma unroll
            for (int nt = 0; nt < 4; nt++) {
                const int c0 = nwarp * 32 + nt * 8 + (lane & 3) * 2;
                sE[c0 * 132 + r0] = acc[mt][nt][0];
                sE[(c0 + 1) * 132 + r0] = acc[mt][nt][1];
                sE[c0 * 132 + r0 + 8] = acc[mt][nt][2];
                sE[(c0 + 1) * 132 + r0 + 8] = acc[mt][nt][3];
            }
        }
        __syncthreads();
#pragma unroll
        for (int q = 0; q < 8; q++) {
            const int idx = q * 256 + tid;      // 2048 float4 slots
            const int oc = idx >> 5;
            const int g = idx & 31;
            float4 v = *(float4*)&sE[oc * 132 + g * 4];
            const float bv4 = s_bias[oc];
            v.x = fmaxf(v.x + bv4, 0.f);
            v.y = fmaxf(v.y + bv4, 0.f);
            v.z = fmaxf(v.z + bv4, 0.f);
            v.w = fmaxf(v.w + bv4, 0.f);
            float* dst = out + (size_t)(n * OCTOT + nblk * 64 + oc) * (OH * OW)
                       + oh0 * OW;
            *(float4*)(dst + g * 4) = v;
        }
    } else {
        // ReLU + bias + partial global-avg-pool over this block's 128 rows
        float* s_red = (float*)(smem + OFF_RAW);   // [64 col][4 mwarp]
#pragma unroll
        for (int nt = 0; nt < 4; nt++) {
            const int c0 = nwarp * 32 + nt * 8 + (lane & 3) * 2;
            const float b0 = s_bias[c0], b1 = s_bias[c0 + 1];
            float s0 = 0.f, s1 = 0.f;
#pragma unroll
            for (int mt = 0; mt < 2; mt++) {
                s0 += fmaxf(acc[mt][nt][0] + b0, 0.f) + fmaxf(acc[mt][nt][2] + b0, 0.f);
                s1 += fmaxf(acc[mt][nt][1] + b1, 0.f) + fmaxf(acc[mt][nt][3] + b1, 0.f);
            }
#pragma unroll
            for (int off = 16; off >= 4; off >>= 1) {
                s0 += __shfl_xor_sync(0xffffffffu, s0, off);
                s1 += __shfl_xor_sync(0xffffffffu, s1, off);
            }
            if ((lane >> 2) == 0) {
                s_red[c0 * 4 + mwarp] = s0;
                s_red[(c0 + 1) * 4 + mwarp] = s1;
            }
        }
        __syncthreads();
        if (tid < 64) {
            float s = s_red[tid * 4] + s_red[tid * 4 + 1]
                    + s_red[tid * 4 + 2] + s_red[tid * 4 + 3];
            out[((size_t)n * MBLK + mblk) * 256 + nblk * 64 + tid] = s;
        }
    }
}

constexpr int conv_smem(int raw_ics, int rc) {
    int rawb = raw_ics * rc * 2;
    if (rawb < 1024) rawb = 1024;
    return OFF_RAW + rawb + 16;
}

// ---------------------------------------------------------------------------
// Fused per-sample MLP chain (4-way ILP accumulators).
// ---------------------------------------------------------------------------
__global__ void __launch_bounds__(256)
mlp_chain_kernel(const float* __restrict__ vpart, const float* __restrict__ prop,
                 const int* __restrict__ task_ids,
                 const float* __restrict__ p1_w, const float* __restrict__ p1_b,
                 const float* __restrict__ p2_w, const float* __restrict__ p2_b,
                 const float* __restrict__ f1_w, const float* __restrict__ f1_b,
                 const float* __restrict__ f2_w, const float* __restrict__ f2_b,
                 const float* __restrict__ task_emb,
                 const float* __restrict__ g_w, const float* __restrict__ g_b,
                 const float* __restrict__ h1_w, const float* __restrict__ h1_b,
                 const float* __restrict__ h2_w, const float* __restrict__ h2_b,
                 const float* __restrict__ h3_w, const float* __restrict__ h3_b,
                 float* __restrict__ out)
{
    const int n = blockIdx.x;
    const int tid = threadIdx.x;

    __shared__ float sA[320];
    __shared__ float sB[256];
    __shared__ float sx[7];
    __shared__ float sh[64];

    sA[tid] = (vpart[((size_t)n * 2 + 0) * 256 + tid] +
               vpart[((size_t)n * 2 + 1) * 256 + tid]) * (1.f / 256.f);
    if (tid < 7) sx[tid] = prop[n * 7 + tid];
    __syncthreads();

    if (tid < 64) {
        float a = p1_b[tid];
#pragma unroll
        for (int i = 0; i < 7; i++) a += sx[i] * p1_w[i * 64 + tid];
        sh[tid] = fmaxf(a, 0.f);
    }
    __syncthreads();
    if (tid < 64) {
        float a0 = p2_b[tid], a1 = 0.f, a2 = 0.f, a3 = 0.f;
        for (int i = 0; i < 64; i += 4) {
            a0 += sh[i] * p2_w[i * 64 + tid];
            a1 += sh[i + 1] * p2_w[(i + 1) * 64 + tid];
            a2 += sh[i + 2] * p2_w[(i + 2) * 64 + tid];
            a3 += sh[i + 3] * p2_w[(i + 3) * 64 + tid];
        }
        sA[256 + tid] = (a0 + a1) + (a2 + a3);
    }
    __syncthreads();

    {
        float a0 = f1_b[tid], a1 = 0.f, a2 = 0.f, a3 = 0.f;
        for (int i = 0; i < 320; i += 4) {
            a0 += sA[i] * f1_w[i * 256 + tid];
            a1 += sA[i + 1] * f1_w[(i + 1) * 256 + tid];
            a2 += sA[i + 2] * f1_w[(i + 2) * 256 + tid];
            a3 += sA[i + 3] * f1_w[(i + 3) * 256 + tid];
        }
        sB[tid] = fmaxf((a0 + a1) + (a2 + a3), 0.f);
    }
    __syncthreads();
    {
        float a0 = f2_b[tid], a1 = 0.f, a2 = 0.f, a3 = 0.f;
        for (int i = 0; i < 256; i += 4) {
            a0 += sB[i] * f2_w[i * 256 + tid];
            a1 += sB[i + 1] * f2_w[(i + 1) * 256 + tid];
            a2 += sB[i + 2] * f2_w[(i + 2) * 256 + tid];
            a3 += sB[i + 3] * f2_w[(i + 3) * 256 + tid];
        }
        __syncthreads();
        sA[tid] = fmaxf((a0 + a1) + (a2 + a3), 0.f);
    }
    const int t = task_ids[n];
    if (tid < 32) sA[256 + tid] = task_emb[t * 32 + tid];
    __syncthreads();

    {
        float a0 = g_b[tid], a1 = 0.f, a2 = 0.f, a3 = 0.f;
        for (int i = 0; i < 288; i += 4) {
            a0 += sA[i] * g_w[i * 256 + tid];
            a1 += sA[i + 1] * g_w[(i + 1) * 256 + tid];
            a2 += sA[i + 2] * g_w[(i + 2) * 256 + tid];
            a3 += sA[i + 3] * g_w[(i + 3) * 256 + tid];
        }
        sB[tid] = fmaxf((a0 + a1) + (a2 + a3), 0.f);
    }
    __syncthreads();

    const float* w1 = h1_w + (size_t)t * ENC_DIM * HEAD_HID;
    if (tid < 128) {
        float a0 = h1_b[t * HEAD_HID + tid], a1 = 0.f, a2 = 0.f, a3 = 0.f;
        for (int i = 0; i < 256; i += 4) {
            a0 += sB[i] * w1[i * 128 + tid];
            a1 += sB[i + 1] * w1[(i + 1) * 128 + tid];
            a2 += sB[i + 2] * w1[(i + 2) * 128 + tid];
            a3 += sB[i + 3] * w1[(i + 3) * 128 + tid];
        }
        sA[tid] = fmaxf((a0 + a1) + (a2 + a3), 0.f);
    }
    __syncthreads();
    const float* w2 = h2_w + (size_t)t * HEAD_HID * HEAD_HID;
    if (tid < 128) {
        float a0 = h2_b[t * HEAD_HID + tid], a1 = 0.f, a2 = 0.f, a3 = 0.f;
        for (int i = 0; i < 128; i += 4) {
            a0 += sA[i] * w2[i * 128 + tid];
            a1 += sA[i + 1] * w2[(i + 1) * 128 + tid];
            a2 += sA[i + 2] * w2[(i + 2) * 128 + tid];
            a3 += sA[i + 3] * w2[(i + 3) * 128 + tid];
        }
        sB[tid] = fmaxf((a0 + a1) + (a2 + a3), 0.f);
    }
    __syncthreads();
    const float* w3 = h3_w + (size_t)t * HEAD_HID * ACT_DIM;
    if (tid < 4) {
        float a = h3_b[t * ACT_DIM + tid];
        for (int i = 0; i < 128; i++) a += sB[i] * w3[i * 4 + tid];
        out[n * 4 + tid] = a;
    }
}

// ---------------------------------------------------------------------------
extern "C" void kernel_launch(void* const* d_in, const int* in_sizes, int n_in,
                              void* d_out, int out_size)
{
    const float* images = (const float*)d_in[0];
    const float* prop   = (const float*)d_in[1];
    const int*   tids   = (const int*)d_in[2];
    const float* c1_w = (const float*)d_in[3];
    const float* c1_b = (const float*)d_in[4];
    const float* c2_w = (const float*)d_in[5];
    const float* c2_b = (const float*)d_in[6];
    const float* c3_w = (const float*)d_in[7];
    const float* c3_b = (const float*)d_in[8];
    const float* p1_w = (const float*)d_in[9];
    const float* p1_b = (const float*)d_in[10];
    const float* p2_w = (const float*)d_in[11];
    const float* p2_b = (const float*)d_in[12];
    const float* f1_w = (const float*)d_in[13];
    const float* f1_b = (const float*)d_in[14];
    const float* f2_w = (const float*)d_in[15];
    const float* f2_b = (const float*)d_in[16];
    const float* temb = (const float*)d_in[17];
    const float* g_w  = (const float*)d_in[18];
    const float* g_b  = (const float*)d_in[19];
    const float* h1_w = (const float*)d_in[20];
    const float* h1_b = (const float*)d_in[21];
    const float* h2_w = (const float*)d_in[22];
    const float* h2_b = (const float*)d_in[23];
    const float* h3_w = (const float*)d_in[24];
    const float* h3_b = (const float*)d_in[25];
    float* out = (float*)d_out;

    float *conv1_out, *conv2_out, *vpart;
    cudaGetSymbolAddress((void**)&conv1_out, g_conv1);
    cudaGetSymbolAddress((void**)&conv2_out, g_conv2);
    cudaGetSymbolAddress((void**)&vpart, g_vpart);

    // conv1: [256,3,128,128] -> [256,64,64,64]; MBLK=32, NBLK=1
    {
        constexpr int SM = conv_smem(3, 5 * 129);
        auto k = conv_hmma_kernel<3, 64, 128, 128, 2, 3, false>;
        cudaFuncSetAttribute(k, cudaFuncAttributeMaxDynamicSharedMemorySize, SM);
        k<<<BATCH * 32, 256, SM>>>(images, c1_w, c1_b, conv1_out);
    }
    // conv2: -> [256,128,32,32]; MBLK=8, NBLK=2
    {
        constexpr int SM = conv_smem(8, 9 * 65);
        auto k = conv_hmma_kernel<64, 128, 64, 64, 4, 8, false>;
        cudaFuncSetAttribute(k, cudaFuncAttributeMaxDynamicSharedMemorySize, SM);
        k<<<BATCH * 8 * 2, 256, SM>>>(conv1_out, c2_w, c2_b, conv2_out);
    }
    // conv3 + fused pool partials -> g_vpart; MBLK=2, NBLK=4
    {
        constexpr int SM = conv_smem(8, 17 * 33);
        auto k = conv_hmma_kernel<128, 256, 32, 32, 8, 8, true>;
        cudaFuncSetAttribute(k, cudaFuncAttributeMaxDynamicSharedMemorySize, SM);
        k<<<BATCH * 2 * 4, 256, SM>>>(conv2_out, c3_w, c3_b, vpart);
    }

    mlp_chain_kernel<<<BATCH, 256>>>(
        vpart, prop, tids,
        p1_w, p1_b, p2_w, p2_b,
        f1_w, f1_b, f2_w, f2_b,
        temb, g_w, g_b,
        h1_w, h1_b, h2_w, h2_b, h3_w, h3_b,
        out);
}

// round 5
// speedup vs baseline: 6.1946x; 3.5318x over previous
#include <cuda_runtime.h>
#include <cuda_fp16.h>
#include <cstdint>

#define BATCH 256
#define ENC_DIM 256
#define HEAD_HID 128

// ---------------------------------------------------------------------------
// Scratch (static __device__ — no allocations allowed)
// ---------------------------------------------------------------------------
__device__ __half g_imgT[(size_t)BATCH * 130 * 130 * 4];        // padded NHWC4
__device__ __half g_act1[(size_t)BATCH * 64 * 64 * 64];         // conv1 out NHWC
__device__ __half g_act2[(size_t)BATCH * 32 * 32 * 128];        // conv2 out NHWC
__device__ __half g_w1rep[64 * 64];
__device__ __half g_w2rep[128 * 576];
__device__ __half g_w3rep[256 * 1152];
__device__ float  g_vpart[(size_t)BATCH * 2 * 256];

// ---------------------------------------------------------------------------
// helpers
// ---------------------------------------------------------------------------
__device__ __forceinline__ uint32_t smem_u32(const void* p) {
    uint32_t a;
    asm("{ .reg .u64 t; cvta.to.shared.u64 t, %1; cvt.u32.u64 %0, t; }"
        : "=r"(a) : "l"(p));
    return a;
}
__device__ __forceinline__ uint32_t swz(uint32_t off) {
    return off ^ ((off >> 3) & 0x70);
}
__device__ __forceinline__ void ldm_x4(uint32_t r[4], uint32_t addr) {
    asm volatile("ldmatrix.sync.aligned.m8n8.x4.shared.b16 {%0,%1,%2,%3}, [%4];"
                 : "=r"(r[0]), "=r"(r[1]), "=r"(r[2]), "=r"(r[3]) : "r"(addr));
}
__device__ __forceinline__ void mma_f16(float c[4], const uint32_t a[4],
                                        uint32_t b0, uint32_t b1) {
    asm volatile(
        "mma.sync.aligned.m16n8k16.row.col.f32.f16.f16.f32 "
        "{%0,%1,%2,%3},{%4,%5,%6,%7},{%8,%9},{%0,%1,%2,%3};"
        : "+f"(c[0]), "+f"(c[1]), "+f"(c[2]), "+f"(c[3])
        : "r"(a[0]), "r"(a[1]), "r"(a[2]), "r"(a[3]), "r"(b0), "r"(b1));
}
#define CP_COMMIT() asm volatile("cp.async.commit_group;" ::: "memory")
#define CP_WAIT0()  asm volatile("cp.async.wait_group 0;" ::: "memory")
#define CP_WAIT1()  asm volatile("cp.async.wait_group 1;" ::: "memory")

// ---------------------------------------------------------------------------
// Repack kernels (one-time per launch, cheap)
// ---------------------------------------------------------------------------
__global__ void repack_img(const float* __restrict__ img, __half* __restrict__ dst)
{
    int idx = blockIdx.x * 256 + threadIdx.x;
    if (idx >= BATCH * 130 * 130) return;
    int n = idx / 16900;
    int r = idx - n * 16900;
    int ihp = r / 130;
    int iwp = r - ihp * 130;
    int ih = ihp - 1, iw = iwp - 1;
    float c0 = 0.f, c1 = 0.f, c2 = 0.f;
    if ((unsigned)ih < 128u && (unsigned)iw < 128u) {
        size_t b = (size_t)n * 3 * 16384 + ih * 128 + iw;
        c0 = img[b]; c1 = img[b + 16384]; c2 = img[b + 32768];
    }
    __half2 lo = __floats2half2_rn(c0, c1);
    __half2 hi = __floats2half2_rn(c2, 0.f);
    uint2 v;
    v.x = *(uint32_t*)&lo;
    v.y = *(uint32_t*)&hi;
    *(uint2*)(dst + (size_t)idx * 4) = v;
}

__global__ void repack_w(const float* __restrict__ src, __half* __restrict__ dst,
                         int OC, int IC, int ICP, int K)
{
    int idx = blockIdx.x * 256 + threadIdx.x;
    if (idx >= OC * K) return;
    int oc = idx / K;
    int k = idx - oc * K;
    int tap = k / ICP;
    int ic = k - tap * ICP;
    float v = (tap < 9 && ic < IC) ? src[(oc * IC + ic) * 9 + tap] : 0.f;
    dst[idx] = __float2half_rn(v);
}

// ---------------------------------------------------------------------------
// cp.async implicit-GEMM conv 3x3 s2 p1 on NHWC-half activations.
// Block 256 thr (8 warps: 4M x 2N). Tile M=128 spatial x N=NB oc.
// K = ICTOT*9, tap-major (k = tap*ICP + ic), chunks of 64 halves (128B rows).
// 2-stage cp.async pipeline. Output NHWC half, or fused avg-pool partials.
// ---------------------------------------------------------------------------
template <int ICP, int KTOT, int OCTOT, int NB, int IH, int IW, int OH_TILE,
          bool FUSE_POOL, bool IS_CONV1>
__global__ void __launch_bounds__(256, 2)
conv_cp_kernel(const __half* __restrict__ in, const __half* __restrict__ wrep,
               const float* __restrict__ bias, void* __restrict__ outp)
{
    constexpr int OH = IH / 2, OW = IW / 2;
    constexpr int LOG_OW = (OW == 64) ? 6 : (OW == 32) ? 5 : 4;
    constexpr int NCH = KTOT / 64;
    constexpr int CPT = (ICP >= 64) ? ICP / 64 : 1;   // chunks per tap
    constexpr int MBLK = OH / OH_TILE;
    constexpr int NBLK = OCTOT / NB;
    constexpr int NT = NB / 16;
    constexpr int NP = NB / 32;
    constexpr uint32_t OFFA0 = 1024, OFFA1 = 17408, OFFB0 = 33792;
    constexpr uint32_t BB = NB * 128;

    extern __shared__ char smem[];
    const uint32_t sb = smem_u32(smem);
    float* s_bias = (float*)smem;

    const int bid = blockIdx.x;
    const int n = bid / (MBLK * NBLK);
    const int r = bid - n * (MBLK * NBLK);
    const int mblk = r / NBLK;
    const int nblk = r - mblk * NBLK;
    const int oh0 = mblk * OH_TILE;

    const int tid = threadIdx.x;
    const int warp = tid >> 5;
    const int lane = tid & 31;
    const int mwarp = warp >> 1;
    const int nwarp = warp & 1;

    if (tid < NB) s_bias[tid] = bias[nblk * NB + tid];

    // -------- staging lambdas --------
    const int am = tid >> 1;
    const int a_ohl = am >> LOG_OW;
    const int a_ow = am & (OW - 1);

    auto issueA = [&](int c, uint32_t abase) {
        if (IS_CONV1) {
            const int ihb = (oh0 + a_ohl) * 2;     // padded coords (+kh)
            const int iwb = a_ow * 2;              // (+kw)
#pragma unroll
            for (int i = 0; i < 5; i++) {
                int j = (tid & 1) + 2 * i;
                if (j <= 8) {
                    int kh = j / 3, kw = j - kh * 3;
                    const __half* src =
                        in + (((size_t)n * 130 + ihb + kh) * 130 + iwb + kw) * 4;
                    uint32_t dst = sb + abase + swz((uint32_t)(am * 128 + j * 8));
                    asm volatile("cp.async.ca.shared.global [%0], [%1], 8;"
                                 :: "r"(dst), "l"(src));
                }
            }
        } else {
            const int tap = c / CPT;
            const int ic0 = (c & (CPT - 1)) * 64;
            const int kh = tap / 3, kw = tap - kh * 3;
            const int ih = (oh0 + a_ohl) * 2 - 1 + kh;
            const int iw = a_ow * 2 - 1 + kw;
            const bool valid = ((unsigned)ih < (unsigned)IH) &&
                               ((unsigned)iw < (unsigned)IW);
            const __half* src = valid
                ? in + (((size_t)n * IH + ih) * IW + iw) * ICP + ic0 : in;
            const int sz = valid ? 16 : 0;
#pragma unroll
            for (int i = 0; i < 4; i++) {
                int u = (tid & 1) * 4 + i;
                uint32_t dst = sb + abase + swz((uint32_t)(am * 128 + u * 16));
                asm volatile("cp.async.cg.shared.global [%0], [%1], 16, %2;"
                             :: "r"(dst), "l"(src + u * 8), "r"(sz));
            }
        }
    };
    auto issueB = [&](int c, uint32_t bbase) {
        constexpr int UPT = NB / 32;
#pragma unroll
        for (int i = 0; i < UPT; i++) {
            int u = tid * UPT + i;
            int row = u >> 3, j = u & 7;
            const __half* src = wrep + (size_t)(nblk * NB + row) * KTOT + c * 64 + j * 8;
            uint32_t dst = sb + bbase + swz((uint32_t)(row * 128 + j * 16));
            asm volatile("cp.async.cg.shared.global [%0], [%1], 16;"
                         :: "r"(dst), "l"(src));
        }
    };

    // -------- accumulators + mma --------
    float acc[2][NT][4];
#pragma unroll
    for (int mt = 0; mt < 2; mt++)
#pragma unroll
        for (int nt = 0; nt < NT; nt++)
#pragma unroll
            for (int i = 0; i < 4; i++) acc[mt][nt][i] = 0.f;

    auto do_mma = [&](uint32_t abase, uint32_t bbase) {
#pragma unroll
        for (int ks = 0; ks < 4; ks++) {
            const uint32_t colb = ks * 32 + ((lane >> 4) << 4);
            uint32_t a[2][4], bf[NP][4];
#pragma unroll
            for (int mt = 0; mt < 2; mt++) {
                const uint32_t row = mwarp * 32 + mt * 16 + (lane & 15);
                ldm_x4(a[mt], sb + abase + swz(row * 128 + colb));
            }
#pragma unroll
            for (int np = 0; np < NP; np++) {
                const uint32_t row = nwarp * (NB / 2) + np * 16 + (lane & 15);
                ldm_x4(bf[np], sb + bbase + swz(row * 128 + colb));
            }
#pragma unroll
            for (int mt = 0; mt < 2; mt++)
#pragma unroll
                for (int nt = 0; nt < NT; nt++)
                    mma_f16(acc[mt][nt], a[mt], bf[nt >> 1][nt & 1],
                            bf[nt >> 1][2 + (nt & 1)]);
        }
    };

    // -------- conv1: pre-zero A stage (K padded 36->64) --------
    if (IS_CONV1) {
        uint4 z = make_uint4(0, 0, 0, 0);
#pragma unroll
        for (int i = 0; i < 4; i++)
            *(uint4*)(smem + OFFA0 + (tid + i * 256) * 16) = z;
        __syncthreads();
    }

    // -------- pipeline --------
    issueA(0, OFFA0);
    issueB(0, OFFB0);
    CP_COMMIT();

    for (int c = 0; c < NCH; c++) {
        const bool more = (c + 1 < NCH);
        if (more) {
            const uint32_t an = (c + 1) & 1 ? OFFA1 : OFFA0;
            const uint32_t bn = (c + 1) & 1 ? OFFB0 + BB : OFFB0;
            issueA(c + 1, an);
            issueB(c + 1, bn);
            CP_COMMIT();
            CP_WAIT1();
        } else {
            CP_WAIT0();
        }
        __syncthreads();
        do_mma((c & 1) ? OFFA1 : OFFA0, (c & 1) ? OFFB0 + BB : OFFB0);
        __syncthreads();
    }

    // -------- epilogue --------
    if (!FUSE_POOL) {
        constexpr uint32_t ES = NB * 2 + 16;
        char* epi = smem + OFFA0;
#pragma unroll
        for (int mt = 0; mt < 2; mt++) {
            const int r0 = mwarp * 32 + mt * 16 + (lane >> 2);
#pragma unroll
            for (int nt = 0; nt < NT; nt++) {
                const int c0 = nwarp * (NB / 2) + nt * 8 + (lane & 3) * 2;
                const float b0 = s_bias[c0], b1 = s_bias[c0 + 1];
                __half2 v0 = __floats2half2_rn(fmaxf(acc[mt][nt][0] + b0, 0.f),
                                               fmaxf(acc[mt][nt][1] + b1, 0.f));
                __half2 v1 = __floats2half2_rn(fmaxf(acc[mt][nt][2] + b0, 0.f),
                                               fmaxf(acc[mt][nt][3] + b1, 0.f));
                *(__half2*)(epi + r0 * ES + c0 * 2) = v0;
                *(__half2*)(epi + (r0 + 8) * ES + c0 * 2) = v1;
            }
        }
        __syncthreads();
        constexpr int ROWB = NB / 8;          // uint4 per row
        constexpr int T4 = 128 * ROWB / 256;
        __half* outh = (__half*)outp;
#pragma unroll
        for (int i = 0; i < T4; i++) {
            int idx = tid + i * 256;
            int r2 = idx / ROWB;
            int j = idx & (ROWB - 1);
            uint4 v = *(const uint4*)(epi + r2 * ES + j * 16);
            int ohl = r2 >> LOG_OW, ow = r2 & (OW - 1);
            __half* dst = outh + (((size_t)n * OH + oh0 + ohl) * OW + ow) * OCTOT
                        + nblk * NB + j * 8;
            *(uint4*)dst = v;
        }
    } else {
        float* s_red = (float*)(smem + OFFA0);   // [NB][4]
#pragma unroll
        for (int nt = 0; nt < NT; nt++) {
            const int c0 = nwarp * (NB / 2) + nt * 8 + (lane & 3) * 2;
            const float b0 = s_bias[c0], b1 = s_bias[c0 + 1];
            float s0 = 0.f, s1 = 0.f;
#pragma unroll
            for (int mt = 0; mt < 2; mt++) {
                s0 += fmaxf(acc[mt][nt][0] + b0, 0.f) + fmaxf(acc[mt][nt][2] + b0, 0.f);
                s1 += fmaxf(acc[mt][nt][1] + b1, 0.f) + fmaxf(acc[mt][nt][3] + b1, 0.f);
            }
#pragma unroll
            for (int off = 16; off >= 4; off >>= 1) {
                s0 += __shfl_xor_sync(0xffffffffu, s0, off);
                s1 += __shfl_xor_sync(0xffffffffu, s1, off);
            }
            if ((lane >> 2) == 0) {
                s_red[c0 * 4 + mwarp] = s0;
                s_red[(c0 + 1) * 4 + mwarp] = s1;
            }
        }
        __syncthreads();
        if (tid < NB) {
            float s = s_red[tid * 4] + s_red[tid * 4 + 1]
                    + s_red[tid * 4 + 2] + s_red[tid * 4 + 3];
            ((float*)outp)[((size_t)n * MBLK + mblk) * 256 + nblk * NB + tid] = s;
        }
    }
}

// ---------------------------------------------------------------------------
// Fused per-sample MLP chain (split-K heads).
// ---------------------------------------------------------------------------
__global__ void __launch_bounds__(256)
mlp_chain_kernel(const float* __restrict__ vpart, const float* __restrict__ prop,
                 const int* __restrict__ task_ids,
                 const float* __restrict__ p1_w, const float* __restrict__ p1_b,
                 const float* __restrict__ p2_w, const float* __restrict__ p2_b,
                 const float* __restrict__ f1_w, const float* __restrict__ f1_b,
                 const float* __restrict__ f2_w, const float* __restrict__ f2_b,
                 const float* __restrict__ task_emb,
                 const float* __restrict__ g_w, const float* __restrict__ g_b,
                 const float* __restrict__ h1_w, const float* __restrict__ h1_b,
                 const float* __restrict__ h2_w, const float* __restrict__ h2_b,
                 const float* __restrict__ h3_w, const float* __restrict__ h3_b,
                 float* __restrict__ out)
{
    const int n = blockIdx.x;
    const int tid = threadIdx.x;

    __shared__ float sA[320];
    __shared__ float sB[256];
    __shared__ float sx[7];
    __shared__ float sh[64];

    sA[tid] = (vpart[((size_t)n * 2 + 0) * 256 + tid] +
               vpart[((size_t)n * 2 + 1) * 256 + tid]) * (1.f / 256.f);
    if (tid < 7) sx[tid] = prop[n * 7 + tid];
    __syncthreads();

    if (tid < 64) {
        float a = p1_b[tid];
#pragma unroll
        for (int i = 0; i < 7; i++) a += sx[i] * p1_w[i * 64 + tid];
        sh[tid] = fmaxf(a, 0.f);
    }
    __syncthreads();
    if (tid < 64) {
        float a0 = p2_b[tid], a1 = 0.f, a2 = 0.f, a3 = 0.f;
        for (int i = 0; i < 64; i += 4) {
            a0 += sh[i] * p2_w[i * 64 + tid];
            a1 += sh[i + 1] * p2_w[(i + 1) * 64 + tid];
            a2 += sh[i + 2] * p2_w[(i + 2) * 64 + tid];
            a3 += sh[i + 3] * p2_w[(i + 3) * 64 + tid];
        }
        sA[256 + tid] = (a0 + a1) + (a2 + a3);
    }
    __syncthreads();

    {
        float a0 = f1_b[tid], a1 = 0.f, a2 = 0.f, a3 = 0.f;
        for (int i = 0; i < 320; i += 4) {
            a0 += sA[i] * f1_w[i * 256 + tid];
            a1 += sA[i + 1] * f1_w[(i + 1) * 256 + tid];
            a2 += sA[i + 2] * f1_w[(i + 2) * 256 + tid];
            a3 += sA[i + 3] * f1_w[(i + 3) * 256 + tid];
        }
        sB[tid] = fmaxf((a0 + a1) + (a2 + a3), 0.f);
    }
    __syncthreads();
    float f2v;
    {
        float a0 = f2_b[tid], a1 = 0.f, a2 = 0.f, a3 = 0.f;
        for (int i = 0; i < 256; i += 4) {
            a0 += sB[i] * f2_w[i * 256 + tid];
            a1 += sB[i + 1] * f2_w[(i + 1) * 256 + tid];
            a2 += sB[i + 2] * f2_w[(i + 2) * 256 + tid];
            a3 += sB[i + 3] * f2_w[(i + 3) * 256 + tid];
        }
        f2v = fmaxf((a0 + a1) + (a2 + a3), 0.f);
    }
    __syncthreads();
    sA[tid] = f2v;
    const int t = task_ids[n];
    if (tid < 32) sA[256 + tid] = task_emb[t * 32 + tid];
    __syncthreads();

    {
        float a0 = g_b[tid], a1 = 0.f, a2 = 0.f, a3 = 0.f;
        for (int i = 0; i < 288; i += 4) {
            a0 += sA[i] * g_w[i * 256 + tid];
            a1 += sA[i + 1] * g_w[(i + 1) * 256 + tid];
            a2 += sA[i + 2] * g_w[(i + 2) * 256 + tid];
            a3 += sA[i + 3] * g_w[(i + 3) * 256 + tid];
        }
        sB[tid] = fmaxf((a0 + a1) + (a2 + a3), 0.f);
    }
    __syncthreads();

    // h1: 256 -> 128, 2-way split-K
    {
        const float* w1 = h1_w + (size_t)t * ENC_DIM * HEAD_HID;
        const int o = tid >> 1;
        const int k0 = (tid & 1) * 128;
        float a0 = 0.f, a1 = 0.f, a2 = 0.f, a3 = 0.f;
        for (int i = 0; i < 128; i += 4) {
            int k = k0 + i;
            a0 += sB[k] * w1[k * 128 + o];
            a1 += sB[k + 1] * w1[(k + 1) * 128 + o];
            a2 += sB[k + 2] * w1[(k + 2) * 128 + o];
            a3 += sB[k + 3] * w1[(k + 3) * 128 + o];
        }
        float a = (a0 + a1) + (a2 + a3);
        a += __shfl_xor_sync(0xffffffffu, a, 1);
        if (!(tid & 1)) sA[o] = fmaxf(a + h1_b[t * 128 + o], 0.f);
    }
    __syncthreads();
    // h2: 128 -> 128, 2-way split-K
    {
        const float* w2 = h2_w + (size_t)t * HEAD_HID * HEAD_HID;
        const int o = tid >> 1;
        const int k0 = (tid & 1) * 64;
        float a0 = 0.f, a1 = 0.f, a2 = 0.f, a3 = 0.f;
        for (int i = 0; i < 64; i += 4) {
            int k = k0 + i;
            a0 += sA[k] * w2[k * 128 + o];
            a1 += sA[k + 1] * w2[(k + 1) * 128 + o];
            a2 += sA[k + 2] * w2[(k + 2) * 128 + o];
            a3 += sA[k + 3] * w2[(k + 3) * 128 + o];
        }
        float a = (a0 + a1) + (a2 + a3);
        a += __shfl_xor_sync(0xffffffffu, a, 1);
        if (!(tid & 1)) sB[o] = fmaxf(a + h2_b[t * 128 + o], 0.f);
    }
    __syncthreads();
    // h3: 128 -> 4, one warp per output
    if (tid < 128) {
        const float* w3 = h3_w + (size_t)t * HEAD_HID * 4;
        const int o = tid >> 5;
        const int l = tid & 31;
        float a = 0.f;
#pragma unroll
        for (int j = 0; j < 4; j++) a += sB[l + j * 32] * w3[(l + j * 32) * 4 + o];
#pragma unroll
        for (int d = 16; d > 0; d >>= 1) a += __shfl_xor_sync(0xffffffffu, a, d);
        if (l == 0) out[n * 4 + o] = a + h3_b[t * 4 + o];
    }
}

// ---------------------------------------------------------------------------
extern "C" void kernel_launch(void* const* d_in, const int* in_sizes, int n_in,
                              void* d_out, int out_size)
{
    const float* images = (const float*)d_in[0];
    const float* prop   = (const float*)d_in[1];
    const int*   tids   = (const int*)d_in[2];
    const float* c1_w = (const float*)d_in[3];
    const float* c1_b = (const float*)d_in[4];
    const float* c2_w = (const float*)d_in[5];
    const float* c2_b = (const float*)d_in[6];
    const float* c3_w = (const float*)d_in[7];
    const float* c3_b = (const float*)d_in[8];
    const float* p1_w = (const float*)d_in[9];
    const float* p1_b = (const float*)d_in[10];
    const float* p2_w = (const float*)d_in[11];
    const float* p2_b = (const float*)d_in[12];
    const float* f1_w = (const float*)d_in[13];
    const float* f1_b = (const float*)d_in[14];
    const float* f2_w = (const float*)d_in[15];
    const float* f2_b = (const float*)d_in[16];
    const float* temb = (const float*)d_in[17];
    const float* g_w  = (const float*)d_in[18];
    const float* g_b  = (const float*)d_in[19];
    const float* h1_w = (const float*)d_in[20];
    const float* h1_b = (const float*)d_in[21];
    const float* h2_w = (const float*)d_in[22];
    const float* h2_b = (const float*)d_in[23];
    const float* h3_w = (const float*)d_in[24];
    const float* h3_b = (const float*)d_in[25];
    float* out = (float*)d_out;

    __half *imgT, *act1, *act2, *w1r, *w2r, *w3r;
    float* vpart;
    cudaGetSymbolAddress((void**)&imgT, g_imgT);
    cudaGetSymbolAddress((void**)&act1, g_act1);
    cudaGetSymbolAddress((void**)&act2, g_act2);
    cudaGetSymbolAddress((void**)&w1r, g_w1rep);
    cudaGetSymbolAddress((void**)&w2r, g_w2rep);
    cudaGetSymbolAddress((void**)&w3r, g_w3rep);
    cudaGetSymbolAddress((void**)&vpart, g_vpart);

    // repacks
    repack_img<<<(BATCH * 130 * 130 + 255) / 256, 256>>>(images, imgT);
    repack_w<<<(64 * 64 + 255) / 256, 256>>>(c1_w, w1r, 64, 3, 4, 64);
    repack_w<<<(128 * 576 + 255) / 256, 256>>>(c2_w, w2r, 128, 64, 64, 576);
    repack_w<<<(256 * 1152 + 255) / 256, 256>>>(c3_w, w3r, 256, 128, 128, 1152);

    // conv1: imgT -> act1 [256,64,64,64] NHWC half. NB=64, MBLK=32
    {
        constexpr int SM = 33792 + 2 * (64 * 128);
        auto k = conv_cp_kernel<4, 64, 64, 64, 128, 128, 2, false, true>;
        cudaFuncSetAttribute(k, cudaFuncAttributeMaxDynamicSharedMemorySize, SM);
        k<<<BATCH * 32, 256, SM>>>(imgT, w1r, c1_b, act1);
    }
    // conv2: act1 -> act2 [256,32,32,128] NHWC half. NB=128, MBLK=8
    {
        constexpr int SM = 33792 + 2 * (128 * 128);
        auto k = conv_cp_kernel<64, 576, 128, 128, 64, 64, 4, false, false>;
        cudaFuncSetAttribute(k, cudaFuncAttributeMaxDynamicSharedMemorySize, SM);
        k<<<BATCH * 8, 256, SM>>>(act1, w2r, c2_b, act2);
    }
    // conv3 + pool partials -> vpart. NB=128, MBLK=2, NBLK=2
    {
        constexpr int SM = 33792 + 2 * (128 * 128);
        auto k = conv_cp_kernel<128, 1152, 256, 128, 32, 32, 8, true, false>;
        cudaFuncSetAttribute(k, cudaFuncAttributeMaxDynamicSharedMemorySize, SM);
        k<<<BATCH * 2 * 2, 256, SM>>>(act2, w3r, c3_b, vpart);
    }

    mlp_chain_kernel<<<BATCH, 256>>>(
        vpart, prop, tids,
        p1_w, p1_b, p2_w, p2_b,
        f1_w, f1_b, f2_w, f2_b,
        temb, g_w, g_b,
        h1_w, h1_b, h2_w, h2_b, h3_w, h3_b,
        out);
}

// round 6
// speedup vs baseline: 6.8982x; 1.1136x over previous
#include <cuda_runtime.h>
#include <cuda_fp16.h>
#include <cstdint>

#define BATCH 256
#define ENC_DIM 256
#define HEAD_HID 128

// ---------------------------------------------------------------------------
// Scratch (static __device__ — no allocations allowed)
// ---------------------------------------------------------------------------
__device__ __half g_imgT[(size_t)BATCH * 130 * 130 * 4];        // padded NHWC4
__device__ __half g_act1[(size_t)BATCH * 64 * 64 * 64];         // conv1 out NHWC
__device__ __half g_act2[(size_t)BATCH * 32 * 32 * 128];        // conv2 out NHWC
__device__ __half g_w1rep[64 * 64];
__device__ __half g_w2rep[128 * 576];
__device__ __half g_w3rep[256 * 1152];
__device__ float  g_vpart[(size_t)BATCH * 2 * 256];

// ---------------------------------------------------------------------------
// helpers
// ---------------------------------------------------------------------------
__device__ __forceinline__ uint32_t smem_u32(const void* p) {
    uint32_t a;
    asm("{ .reg .u64 t; cvta.to.shared.u64 t, %1; cvt.u32.u64 %0, t; }"
        : "=r"(a) : "l"(p));
    return a;
}
__device__ __forceinline__ uint32_t swz(uint32_t off) {
    return off ^ ((off >> 3) & 0x70);
}
__device__ __forceinline__ void ldm_x4(uint32_t r[4], uint32_t addr) {
    asm volatile("ldmatrix.sync.aligned.m8n8.x4.shared.b16 {%0,%1,%2,%3}, [%4];"
                 : "=r"(r[0]), "=r"(r[1]), "=r"(r[2]), "=r"(r[3]) : "r"(addr));
}
__device__ __forceinline__ void mma_f16(float c[4], const uint32_t a[4],
                                        uint32_t b0, uint32_t b1) {
    asm volatile(
        "mma.sync.aligned.m16n8k16.row.col.f32.f16.f16.f32 "
        "{%0,%1,%2,%3},{%4,%5,%6,%7},{%8,%9},{%0,%1,%2,%3};"
        : "+f"(c[0]), "+f"(c[1]), "+f"(c[2]), "+f"(c[3])
        : "r"(a[0]), "r"(a[1]), "r"(a[2]), "r"(a[3]), "r"(b0), "r"(b1));
}
#define CP_COMMIT() asm volatile("cp.async.commit_group;" ::: "memory")
#define CP_WAIT0()  asm volatile("cp.async.wait_group 0;" ::: "memory")
#define CP_WAIT1()  asm volatile("cp.async.wait_group 1;" ::: "memory")
#define CP_WAIT2()  asm volatile("cp.async.wait_group 2;" ::: "memory")

// ---------------------------------------------------------------------------
// Repack kernels (one-time per launch, cheap)
// ---------------------------------------------------------------------------
__global__ void repack_img(const float* __restrict__ img, __half* __restrict__ dst)
{
    int idx = blockIdx.x * 256 + threadIdx.x;
    if (idx >= BATCH * 130 * 130) return;
    int n = idx / 16900;
    int r = idx - n * 16900;
    int ihp = r / 130;
    int iwp = r - ihp * 130;
    int ih = ihp - 1, iw = iwp - 1;
    float c0 = 0.f, c1 = 0.f, c2 = 0.f;
    if ((unsigned)ih < 128u && (unsigned)iw < 128u) {
        size_t b = (size_t)n * 3 * 16384 + ih * 128 + iw;
        c0 = img[b]; c1 = img[b + 16384]; c2 = img[b + 32768];
    }
    __half2 lo = __floats2half2_rn(c0, c1);
    __half2 hi = __floats2half2_rn(c2, 0.f);
    uint2 v;
    v.x = *(uint32_t*)&lo;
    v.y = *(uint32_t*)&hi;
    *(uint2*)(dst + (size_t)idx * 4) = v;
}

__device__ __forceinline__ void repack_one(const float* __restrict__ src,
                                           __half* __restrict__ dst,
                                           int idx, int IC, int ICP, int K)
{
    int oc = idx / K;
    int k = idx - oc * K;
    int tap = k / ICP;
    int ic = k - tap * ICP;
    float v = (tap < 9 && ic < IC) ? src[(oc * IC + ic) * 9 + tap] : 0.f;
    dst[idx] = __float2half_rn(v);
}

__global__ void repack_w_all(const float* __restrict__ c1w,
                             const float* __restrict__ c2w,
                             const float* __restrict__ c3w,
                             __half* __restrict__ w1, __half* __restrict__ w2,
                             __half* __restrict__ w3)
{
    int idx = blockIdx.x * 256 + threadIdx.x;
    if (idx < 4096) repack_one(c1w, w1, idx, 3, 4, 64);
    else if (idx < 4096 + 73728) repack_one(c2w, w2, idx - 4096, 64, 64, 576);
    else if (idx < 4096 + 73728 + 294912)
        repack_one(c3w, w3, idx - 4096 - 73728, 128, 128, 1152);
}

// ---------------------------------------------------------------------------
// cp.async implicit-GEMM conv 3x3 s2 p1 on NHWC-half activations.
// Block 256 thr (8 warps: 4M x 2N). Tile M=128 spatial x N=NB oc.
// K = ICTOT*9, tap-major (k = tap*ICP + ic), chunks of 64 halves (128B rows).
// 3-stage cp.async pipeline. Output NHWC half, or fused avg-pool partials.
// ---------------------------------------------------------------------------
template <int ICP, int KTOT, int OCTOT, int NB, int IH, int IW, int OH_TILE,
          bool FUSE_POOL, bool IS_CONV1>
__global__ void __launch_bounds__(256, 2)
conv_cp_kernel(const __half* __restrict__ in, const __half* __restrict__ wrep,
               const float* __restrict__ bias, void* __restrict__ outp)
{
    constexpr int OH = IH / 2, OW = IW / 2;
    constexpr int LOG_OW = (OW == 64) ? 6 : (OW == 32) ? 5 : 4;
    constexpr int NCH = KTOT / 64;
    constexpr int CPT = (ICP >= 64) ? ICP / 64 : 1;   // chunks per tap
    constexpr int MBLK = OH / OH_TILE;
    constexpr int NBLK = OCTOT / NB;
    constexpr int NT = NB / 16;
    constexpr int NP = NB / 32;
    constexpr uint32_t OFFA = 1024;
    constexpr uint32_t ABUF = 16384;
    constexpr uint32_t OFFB = OFFA + 3 * ABUF;        // 50176
    constexpr uint32_t BBUF = NB * 128;

    extern __shared__ char smem[];
    const uint32_t sb = smem_u32(smem);
    float* s_bias = (float*)smem;

    const int bid = blockIdx.x;
    const int n = bid / (MBLK * NBLK);
    const int r = bid - n * (MBLK * NBLK);
    const int mblk = r / NBLK;
    const int nblk = r - mblk * NBLK;
    const int oh0 = mblk * OH_TILE;

    const int tid = threadIdx.x;
    const int warp = tid >> 5;
    const int lane = tid & 31;
    const int mwarp = warp >> 1;
    const int nwarp = warp & 1;

    if (tid < NB) s_bias[tid] = bias[nblk * NB + tid];

    // -------- staging lambdas --------
    const int am = tid >> 1;
    const int a_ohl = am >> LOG_OW;
    const int a_ow = am & (OW - 1);

    auto issueA = [&](int c, uint32_t abase) {
        if (IS_CONV1) {
            const int ihb = (oh0 + a_ohl) * 2;     // padded coords (+kh)
            const int iwb = a_ow * 2;              // (+kw)
#pragma unroll
            for (int i = 0; i < 5; i++) {
                int j = (tid & 1) + 2 * i;
                if (j <= 8) {
                    int kh = j / 3, kw = j - kh * 3;
                    const __half* src =
                        in + (((size_t)n * 130 + ihb + kh) * 130 + iwb + kw) * 4;
                    uint32_t dst = sb + abase + swz((uint32_t)(am * 128 + j * 8));
                    asm volatile("cp.async.ca.shared.global [%0], [%1], 8;"
                                 :: "r"(dst), "l"(src));
                }
            }
        } else {
            const int tap = c / CPT;
            const int ic0 = (c & (CPT - 1)) * 64;
            const int kh = tap / 3, kw = tap - kh * 3;
            const int ih = (oh0 + a_ohl) * 2 - 1 + kh;
            const int iw = a_ow * 2 - 1 + kw;
            const bool valid = ((unsigned)ih < (unsigned)IH) &&
                               ((unsigned)iw < (unsigned)IW);
            const __half* src = valid
                ? in + (((size_t)n * IH + ih) * IW + iw) * ICP + ic0 : in;
            const int sz = valid ? 16 : 0;
#pragma unroll
            for (int i = 0; i < 4; i++) {
                int u = (tid & 1) * 4 + i;
                uint32_t dst = sb + abase + swz((uint32_t)(am * 128 + u * 16));
                asm volatile("cp.async.cg.shared.global [%0], [%1], 16, %2;"
                             :: "r"(dst), "l"(src + u * 8), "r"(sz));
            }
        }
    };
    auto issueB = [&](int c, uint32_t bbase) {
        constexpr int UPT = NB / 32;
#pragma unroll
        for (int i = 0; i < UPT; i++) {
            int u = tid * UPT + i;
            int row = u >> 3, j = u & 7;
            const __half* src = wrep + (size_t)(nblk * NB + row) * KTOT + c * 64 + j * 8;
            uint32_t dst = sb + bbase + swz((uint32_t)(row * 128 + j * 16));
            asm volatile("cp.async.cg.shared.global [%0], [%1], 16;"
                         :: "r"(dst), "l"(src));
        }
    };

    // -------- accumulators + mma --------
    float acc[2][NT][4];
#pragma unroll
    for (int mt = 0; mt < 2; mt++)
#pragma unroll
        for (int nt = 0; nt < NT; nt++)
#pragma unroll
            for (int i = 0; i < 4; i++) acc[mt][nt][i] = 0.f;

    auto do_mma = [&](uint32_t abase, uint32_t bbase) {
#pragma unroll
        for (int ks = 0; ks < 4; ks++) {
            const uint32_t colb = ks * 32 + ((lane >> 4) << 4);
            uint32_t a[2][4], bf[NP][4];
#pragma unroll
            for (int mt = 0; mt < 2; mt++) {
                const uint32_t row = mwarp * 32 + mt * 16 + (lane & 15);
                ldm_x4(a[mt], sb + abase + swz(row * 128 + colb));
            }
#pragma unroll
            for (int np = 0; np < NP; np++) {
                const uint32_t row = nwarp * (NB / 2) + np * 16 + (lane & 15);
                ldm_x4(bf[np], sb + bbase + swz(row * 128 + colb));
            }
#pragma unroll
            for (int mt = 0; mt < 2; mt++)
#pragma unroll
                for (int nt = 0; nt < NT; nt++)
                    mma_f16(acc[mt][nt], a[mt], bf[nt >> 1][nt & 1],
                            bf[nt >> 1][2 + (nt & 1)]);
        }
    };

    // -------- conv1: pre-zero A stage 0 (K padded 36->64) --------
    if (IS_CONV1) {
        uint4 z = make_uint4(0, 0, 0, 0);
#pragma unroll
        for (int i = 0; i < 4; i++)
            *(uint4*)(smem + OFFA + (tid + i * 256) * 16) = z;
        __syncthreads();
    }

    // -------- 3-stage pipeline --------
    issueA(0, OFFA);
    issueB(0, OFFB);
    CP_COMMIT();
    if (NCH > 1) {
        issueA(1, OFFA + ABUF);
        issueB(1, OFFB + BBUF);
        CP_COMMIT();
    }

    int bi = 0;
    for (int c = 0; c < NCH; c++) {
        if (c + 2 < NCH) {
            int b2 = bi + 2; if (b2 >= 3) b2 -= 3;
            issueA(c + 2, OFFA + (uint32_t)b2 * ABUF);
            issueB(c + 2, OFFB + (uint32_t)b2 * BBUF);
            CP_COMMIT();
            CP_WAIT2();
        } else if (c + 1 < NCH) {
            CP_WAIT1();
        } else {
            CP_WAIT0();
        }
        __syncthreads();
        do_mma(OFFA + (uint32_t)bi * ABUF, OFFB + (uint32_t)bi * BBUF);
        __syncthreads();
        if (++bi == 3) bi = 0;
    }

    // -------- epilogue --------
    if (!FUSE_POOL) {
        constexpr uint32_t ES = NB * 2 + 16;
        char* epi = smem + OFFA;
#pragma unroll
        for (int mt = 0; mt < 2; mt++) {
            const int r0 = mwarp * 32 + mt * 16 + (lane >> 2);
#pragma unroll
            for (int nt = 0; nt < NT; nt++) {
                const int c0 = nwarp * (NB / 2) + nt * 8 + (lane & 3) * 2;
                const float b0 = s_bias[c0], b1 = s_bias[c0 + 1];
                __half2 v0 = __floats2half2_rn(fmaxf(acc[mt][nt][0] + b0, 0.f),
                                               fmaxf(acc[mt][nt][1] + b1, 0.f));
                __half2 v1 = __floats2half2_rn(fmaxf(acc[mt][nt][2] + b0, 0.f),
                                               fmaxf(acc[mt][nt][3] + b1, 0.f));
                *(__half2*)(epi + r0 * ES + c0 * 2) = v0;
                *(__half2*)(epi + (r0 + 8) * ES + c0 * 2) = v1;
            }
        }
        __syncthreads();
        constexpr int ROWB = NB / 8;          // uint4 per row
        constexpr int T4 = 128 * ROWB / 256;
        __half* outh = (__half*)outp;
#pragma unroll
        for (int i = 0; i < T4; i++) {
            int idx = tid + i * 256;
            int r2 = idx / ROWB;
            int j = idx & (ROWB - 1);
            uint4 v = *(const uint4*)(epi + r2 * ES + j * 16);
            int ohl = r2 >> LOG_OW, ow = r2 & (OW - 1);
            __half* dst = outh + (((size_t)n * OH + oh0 + ohl) * OW + ow) * OCTOT
                        + nblk * NB + j * 8;
            *(uint4*)dst = v;
        }
    } else {
        float* s_red = (float*)(smem + OFFA);   // [NB][4]
#pragma unroll
        for (int nt = 0; nt < NT; nt++) {
            const int c0 = nwarp * (NB / 2) + nt * 8 + (lane & 3) * 2;
            const float b0 = s_bias[c0], b1 = s_bias[c0 + 1];
            float s0 = 0.f, s1 = 0.f;
#pragma unroll
            for (int mt = 0; mt < 2; mt++) {
                s0 += fmaxf(acc[mt][nt][0] + b0, 0.f) + fmaxf(acc[mt][nt][2] + b0, 0.f);
                s1 += fmaxf(acc[mt][nt][1] + b1, 0.f) + fmaxf(acc[mt][nt][3] + b1, 0.f);
            }
#pragma unroll
            for (int off = 16; off >= 4; off >>= 1) {
                s0 += __shfl_xor_sync(0xffffffffu, s0, off);
                s1 += __shfl_xor_sync(0xffffffffu, s1, off);
            }
            if ((lane >> 2) == 0) {
                s_red[c0 * 4 + mwarp] = s0;
                s_red[(c0 + 1) * 4 + mwarp] = s1;
            }
        }
        __syncthreads();
        if (tid < NB) {
            float s = s_red[tid * 4] + s_red[tid * 4 + 1]
                    + s_red[tid * 4 + 2] + s_red[tid * 4 + 3];
            ((float*)outp)[((size_t)n * MBLK + mblk) * 256 + nblk * NB + tid] = s;
        }
    }
}

// ---------------------------------------------------------------------------
// Fused per-sample MLP chain — 512 threads, split-K on every layer.
// ---------------------------------------------------------------------------
__global__ void __launch_bounds__(512)
mlp_chain_kernel(const float* __restrict__ vpart, const float* __restrict__ prop,
                 const int* __restrict__ task_ids,
                 const float* __restrict__ p1_w, const float* __restrict__ p1_b,
                 const float* __restrict__ p2_w, const float* __restrict__ p2_b,
                 const float* __restrict__ f1_w, const float* __restrict__ f1_b,
                 const float* __restrict__ f2_w, const float* __restrict__ f2_b,
                 const float* __restrict__ task_emb,
                 const float* __restrict__ g_w, const float* __restrict__ g_b,
                 const float* __restrict__ h1_w, const float* __restrict__ h1_b,
                 const float* __restrict__ h2_w, const float* __restrict__ h2_b,
                 const float* __restrict__ h3_w, const float* __restrict__ h3_b,
                 float* __restrict__ out)
{
    const int n = blockIdx.x;
    const int tid = threadIdx.x;

    __shared__ float sA[320];
    __shared__ float sB[256];
    __shared__ float sP[512];
    __shared__ float sx[7];
    __shared__ float sh[64];

    if (tid < 256)
        sA[tid] = (vpart[((size_t)n * 2 + 0) * 256 + tid] +
                   vpart[((size_t)n * 2 + 1) * 256 + tid]) * (1.f / 256.f);
    if (tid < 7) sx[tid] = prop[n * 7 + tid];
    const int t = task_ids[n];
    __syncthreads();

    // p1: 7 -> 64, relu
    if (tid < 64) {
        float a = p1_b[tid];
#pragma unroll
        for (int i = 0; i < 7; i++) a += sx[i] * p1_w[i * 64 + tid];
        sh[tid] = fmaxf(a, 0.f);
    }
    __syncthreads();
    // p2: 64 -> 64 (no relu), split-K 2
    if (tid < 128) {
        const int o = tid & 63, kh = tid >> 6, k0 = kh * 32;
        float a0 = 0.f, a1 = 0.f, a2 = 0.f, a3 = 0.f;
#pragma unroll
        for (int i = 0; i < 32; i += 4) {
            int k = k0 + i;
            a0 += sh[k] * p2_w[k * 64 + o];
            a1 += sh[k + 1] * p2_w[(k + 1) * 64 + o];
            a2 += sh[k + 2] * p2_w[(k + 2) * 64 + o];
            a3 += sh[k + 3] * p2_w[(k + 3) * 64 + o];
        }
        sP[tid] = (a0 + a1) + (a2 + a3);
    }
    __syncthreads();
    if (tid < 64) sA[256 + tid] = sP[tid] + sP[tid + 64] + p2_b[tid];
    __syncthreads();

    // f1: 320 -> 256, relu, split-K 2
    {
        const int o = tid & 255, kh = tid >> 8, k0 = kh * 160;
        float a0 = 0.f, a1 = 0.f, a2 = 0.f, a3 = 0.f;
        for (int i = 0; i < 160; i += 4) {
            int k = k0 + i;
            a0 += sA[k] * f1_w[k * 256 + o];
            a1 += sA[k + 1] * f1_w[(k + 1) * 256 + o];
            a2 += sA[k + 2] * f1_w[(k + 2) * 256 + o];
            a3 += sA[k + 3] * f1_w[(k + 3) * 256 + o];
        }
        sP[tid] = (a0 + a1) + (a2 + a3);
    }
    __syncthreads();
    if (tid < 256) sB[tid] = fmaxf(sP[tid] + sP[tid + 256] + f1_b[tid], 0.f);
    __syncthreads();

    // f2: 256 -> 256, relu, split-K 2
    {
        const int o = tid & 255, kh = tid >> 8, k0 = kh * 128;
        float a0 = 0.f, a1 = 0.f, a2 = 0.f, a3 = 0.f;
        for (int i = 0; i < 128; i += 4) {
            int k = k0 + i;
            a0 += sB[k] * f2_w[k * 256 + o];
            a1 += sB[k + 1] * f2_w[(k + 1) * 256 + o];
            a2 += sB[k + 2] * f2_w[(k + 2) * 256 + o];
            a3 += sB[k + 3] * f2_w[(k + 3) * 256 + o];
        }
        sP[tid] = (a0 + a1) + (a2 + a3);
    }
    __syncthreads();
    if (tid < 256) sA[tid] = fmaxf(sP[tid] + sP[tid + 256] + f2_b[tid], 0.f);
    if (tid >= 256 && tid < 288) sA[tid] = task_emb[t * 32 + (tid - 256)];
    __syncthreads();

    // g: 288 -> 256, relu, split-K 2
    {
        const int o = tid & 255, kh = tid >> 8, k0 = kh * 144;
        float a0 = 0.f, a1 = 0.f, a2 = 0.f, a3 = 0.f;
        for (int i = 0; i < 144; i += 4) {
            int k = k0 + i;
            a0 += sA[k] * g_w[k * 256 + o];
            a1 += sA[k + 1] * g_w[(k + 1) * 256 + o];
            a2 += sA[k + 2] * g_w[(k + 2) * 256 + o];
            a3 += sA[k + 3] * g_w[(k + 3) * 256 + o];
        }
        sP[tid] = (a0 + a1) + (a2 + a3);
    }
    __syncthreads();
    if (tid < 256) sB[tid] = fmaxf(sP[tid] + sP[tid + 256] + g_b[tid], 0.f);
    __syncthreads();

    // h1: 256 -> 128, relu, split-K 4
    {
        const float* w1 = h1_w + (size_t)t * ENC_DIM * HEAD_HID;
        const int o = tid & 127, kh = tid >> 7, k0 = kh * 64;
        float a0 = 0.f, a1 = 0.f, a2 = 0.f, a3 = 0.f;
        for (int i = 0; i < 64; i += 4) {
            int k = k0 + i;
            a0 += sB[k] * w1[k * 128 + o];
            a1 += sB[k + 1] * w1[(k + 1) * 128 + o];
            a2 += sB[k + 2] * w1[(k + 2) * 128 + o];
            a3 += sB[k + 3] * w1[(k + 3) * 128 + o];
        }
        sP[tid] = (a0 + a1) + (a2 + a3);
    }
    __syncthreads();
    if (tid < 128)
        sA[tid] = fmaxf(sP[tid] + sP[tid + 128] + sP[tid + 256] + sP[tid + 384]
                        + h1_b[t * 128 + tid], 0.f);
    __syncthreads();

    // h2: 128 -> 128, relu, split-K 4
    {
        const float* w2 = h2_w + (size_t)t * HEAD_HID * HEAD_HID;
        const int o = tid & 127, kh = tid >> 7, k0 = kh * 32;
        float a0 = 0.f, a1 = 0.f, a2 = 0.f, a3 = 0.f;
#pragma unroll
        for (int i = 0; i < 32; i += 4) {
            int k = k0 + i;
            a0 += sA[k] * w2[k * 128 + o];
            a1 += sA[k + 1] * w2[(k + 1) * 128 + o];
            a2 += sA[k + 2] * w2[(k + 2) * 128 + o];
            a3 += sA[k + 3] * w2[(k + 3) * 128 + o];
        }
        sP[tid] = (a0 + a1) + (a2 + a3);
    }
    __syncthreads();
    if (tid < 128)
        sB[tid] = fmaxf(sP[tid] + sP[tid + 128] + sP[tid + 256] + sP[tid + 384]
                        + h2_b[t * 128 + tid], 0.f);
    __syncthreads();

    // h3: 128 -> 4, one warp per output
    if (tid < 128) {
        const float* w3 = h3_w + (size_t)t * HEAD_HID * 4;
        const int o = tid >> 5;
        const int l = tid & 31;
        float a = 0.f;
#pragma unroll
        for (int j = 0; j < 4; j++) a += sB[l + j * 32] * w3[(l + j * 32) * 4 + o];
#pragma unroll
        for (int d = 16; d > 0; d >>= 1) a += __shfl_xor_sync(0xffffffffu, a, d);
        if (l == 0) out[n * 4 + o] = a + h3_b[t * 4 + o];
    }
}

// ---------------------------------------------------------------------------
extern "C" void kernel_launch(void* const* d_in, const int* in_sizes, int n_in,
                              void* d_out, int out_size)
{
    const float* images = (const float*)d_in[0];
    const float* prop   = (const float*)d_in[1];
    const int*   tids   = (const int*)d_in[2];
    const float* c1_w = (const float*)d_in[3];
    const float* c1_b = (const float*)d_in[4];
    const float* c2_w = (const float*)d_in[5];
    const float* c2_b = (const float*)d_in[6];
    const float* c3_w = (const float*)d_in[7];
    const float* c3_b = (const float*)d_in[8];
    const float* p1_w = (const float*)d_in[9];
    const float* p1_b = (const float*)d_in[10];
    const float* p2_w = (const float*)d_in[11];
    const float* p2_b = (const float*)d_in[12];
    const float* f1_w = (const float*)d_in[13];
    const float* f1_b = (const float*)d_in[14];
    const float* f2_w = (const float*)d_in[15];
    const float* f2_b = (const float*)d_in[16];
    const float* temb = (const float*)d_in[17];
    const float* g_w  = (const float*)d_in[18];
    const float* g_b  = (const float*)d_in[19];
    const float* h1_w = (const float*)d_in[20];
    const float* h1_b = (const float*)d_in[21];
    const float* h2_w = (const float*)d_in[22];
    const float* h2_b = (const float*)d_in[23];
    const float* h3_w = (const float*)d_in[24];
    const float* h3_b = (const float*)d_in[25];
    float* out = (float*)d_out;

    __half *imgT, *act1, *act2, *w1r, *w2r, *w3r;
    float* vpart;
    cudaGetSymbolAddress((void**)&imgT, g_imgT);
    cudaGetSymbolAddress((void**)&act1, g_act1);
    cudaGetSymbolAddress((void**)&act2, g_act2);
    cudaGetSymbolAddress((void**)&w1r, g_w1rep);
    cudaGetSymbolAddress((void**)&w2r, g_w2rep);
    cudaGetSymbolAddress((void**)&w3r, g_w3rep);
    cudaGetSymbolAddress((void**)&vpart, g_vpart);

    // repacks
    repack_img<<<(BATCH * 130 * 130 + 255) / 256, 256>>>(images, imgT);
    repack_w_all<<<(4096 + 73728 + 294912 + 255) / 256, 256>>>(
        c1_w, c2_w, c3_w, w1r, w2r, w3r);

    // conv1: imgT -> act1 [256,64,64,64] NHWC half. NB=64, MBLK=32
    {
        constexpr int SM = 50176 + 3 * (64 * 128);
        auto k = conv_cp_kernel<4, 64, 64, 64, 128, 128, 2, false, true>;
        cudaFuncSetAttribute(k, cudaFuncAttributeMaxDynamicSharedMemorySize, SM);
        k<<<BATCH * 32, 256, SM>>>(imgT, w1r, c1_b, act1);
    }
    // conv2: act1 -> act2 [256,32,32,128] NHWC half. NB=128, MBLK=8
    {
        constexpr int SM = 50176 + 3 * (128 * 128);
        auto k = conv_cp_kernel<64, 576, 128, 128, 64, 64, 4, false, false>;
        cudaFuncSetAttribute(k, cudaFuncAttributeMaxDynamicSharedMemorySize, SM);
        k<<<BATCH * 8, 256, SM>>>(act1, w2r, c2_b, act2);
    }
    // conv3 + pool partials -> vpart. NB=128, MBLK=2, NBLK=2
    {
        constexpr int SM = 50176 + 3 * (128 * 128);
        auto k = conv_cp_kernel<128, 1152, 256, 128, 32, 32, 8, true, false>;
        cudaFuncSetAttribute(k, cudaFuncAttributeMaxDynamicSharedMemorySize, SM);
        k<<<BATCH * 2 * 2, 256, SM>>>(act2, w3r, c3_b, vpart);
    }

    mlp_chain_kernel<<<BATCH, 512>>>(
        vpart, prop, tids,
        p1_w, p1_b, p2_w, p2_b,
        f1_w, f1_b, f2_w, f2_b,
        temb, g_w, g_b,
        h1_w, h1_b, h2_w, h2_b, h3_w, h3_b,
        out);
}

// round 7
// speedup vs baseline: 7.3671x; 1.0680x over previous
#include <cuda_runtime.h>
#include <cuda_fp16.h>
#include <cstdint>

#define BATCH 256
#define ENC_DIM 256
#define HEAD_HID 128

// ---------------------------------------------------------------------------
// Scratch (static __device__ — no allocations allowed)
// ---------------------------------------------------------------------------
__device__ __half g_imgT[(size_t)BATCH * 130 * 130 * 4];        // padded NHWC4
__device__ __half g_act1[(size_t)BATCH * 64 * 64 * 64];         // conv1 out NHWC
__device__ __half g_act2[(size_t)BATCH * 32 * 32 * 128];        // conv2 out NHWC
__device__ __half g_w1rep[64 * 64];
__device__ __half g_w2rep[128 * 576];
__device__ __half g_w3rep[256 * 1152];
__device__ float  g_vpart[(size_t)BATCH * 2 * 256];

// ---------------------------------------------------------------------------
// helpers
// ---------------------------------------------------------------------------
__device__ __forceinline__ uint32_t smem_u32(const void* p) {
    uint32_t a;
    asm("{ .reg .u64 t; cvta.to.shared.u64 t, %1; cvt.u32.u64 %0, t; }"
        : "=r"(a) : "l"(p));
    return a;
}
__device__ __forceinline__ uint32_t swz(uint32_t off) {
    return off ^ ((off >> 3) & 0x70);
}
__device__ __forceinline__ void ldm_x4(uint32_t r[4], uint32_t addr) {
    asm volatile("ldmatrix.sync.aligned.m8n8.x4.shared.b16 {%0,%1,%2,%3}, [%4];"
                 : "=r"(r[0]), "=r"(r[1]), "=r"(r[2]), "=r"(r[3]) : "r"(addr));
}
__device__ __forceinline__ void mma_f16(float c[4], const uint32_t a[4],
                                        uint32_t b0, uint32_t b1) {
    asm volatile(
        "mma.sync.aligned.m16n8k16.row.col.f32.f16.f16.f32 "
        "{%0,%1,%2,%3},{%4,%5,%6,%7},{%8,%9},{%0,%1,%2,%3};"
        : "+f"(c[0]), "+f"(c[1]), "+f"(c[2]), "+f"(c[3])
        : "r"(a[0]), "r"(a[1]), "r"(a[2]), "r"(a[3]), "r"(b0), "r"(b1));
}
#define CP_COMMIT() asm volatile("cp.async.commit_group;" ::: "memory")
#define CP_WAIT0()  asm volatile("cp.async.wait_group 0;" ::: "memory")
#define CP_WAIT1()  asm volatile("cp.async.wait_group 1;" ::: "memory")

// ---------------------------------------------------------------------------
// Repack kernels (one-time per launch, cheap)
// ---------------------------------------------------------------------------
__global__ void repack_img(const float* __restrict__ img, __half* __restrict__ dst)
{
    int idx = blockIdx.x * 512 + threadIdx.x;
    if (idx >= BATCH * 130 * 130) return;
    int n = idx / 16900;
    int r = idx - n * 16900;
    int ihp = r / 130;
    int iwp = r - ihp * 130;
    int ih = ihp - 1, iw = iwp - 1;
    float c0 = 0.f, c1 = 0.f, c2 = 0.f;
    if ((unsigned)ih < 128u && (unsigned)iw < 128u) {
        size_t b = (size_t)n * 3 * 16384 + ih * 128 + iw;
        c0 = img[b]; c1 = img[b + 16384]; c2 = img[b + 32768];
    }
    __half2 lo = __floats2half2_rn(c0, c1);
    __half2 hi = __floats2half2_rn(c2, 0.f);
    uint2 v;
    v.x = *(uint32_t*)&lo;
    v.y = *(uint32_t*)&hi;
    *(uint2*)(dst + (size_t)idx * 4) = v;
}

__device__ __forceinline__ void repack_one(const float* __restrict__ src,
                                           __half* __restrict__ dst,
                                           int idx, int IC, int ICP, int K)
{
    int oc = idx / K;
    int k = idx - oc * K;
    int tap = k / ICP;
    int ic = k - tap * ICP;
    float v = (tap < 9 && ic < IC) ? src[(oc * IC + ic) * 9 + tap] : 0.f;
    dst[idx] = __float2half_rn(v);
}

__global__ void repack_w_all(const float* __restrict__ c1w,
                             const float* __restrict__ c2w,
                             const float* __restrict__ c3w,
                             __half* __restrict__ w1, __half* __restrict__ w2,
                             __half* __restrict__ w3)
{
    int idx = blockIdx.x * 256 + threadIdx.x;
    if (idx < 4096) repack_one(c1w, w1, idx, 3, 4, 64);
    else if (idx < 4096 + 73728) repack_one(c2w, w2, idx - 4096, 64, 64, 576);
    else if (idx < 4096 + 73728 + 294912)
        repack_one(c3w, w3, idx - 4096 - 73728, 128, 128, 1152);
}

// ---------------------------------------------------------------------------
// cp.async implicit-GEMM conv 3x3 s2 p1 on NHWC-half activations.
// Block 256 thr (8 warps: 4M x 2N). Tile M=128 spatial x N=NB oc.
// K = ICTOT*9, tap-major (k = tap*ICP + ic), chunks of 64 halves (128B rows).
// 3-buffer cp.async pipeline with ONE __syncthreads per chunk:
//   wait(chunk c) ; sync ; mma(c) ; issue(c+2)   [buffer (c+2)%3 was last
//   read at c-1, and the sync proves all warps finished c-1]
// ---------------------------------------------------------------------------
template <int ICP, int KTOT, int OCTOT, int NB, int IH, int IW, int OH_TILE,
          bool FUSE_POOL, bool IS_CONV1>
__global__ void __launch_bounds__(256, 2)
conv_cp_kernel(const __half* __restrict__ in, const __half* __restrict__ wrep,
               const float* __restrict__ bias, void* __restrict__ outp)
{
    constexpr int OH = IH / 2, OW = IW / 2;
    constexpr int LOG_OW = (OW == 64) ? 6 : (OW == 32) ? 5 : 4;
    constexpr int NCH = KTOT / 64;
    constexpr int CPT = (ICP >= 64) ? ICP / 64 : 1;   // chunks per tap
    constexpr int MBLK = OH / OH_TILE;
    constexpr int NBLK = OCTOT / NB;
    constexpr int NT = NB / 16;
    constexpr int NP = NB / 32;
    constexpr uint32_t OFFA = 1024;
    constexpr uint32_t ABUF = 16384;
    constexpr uint32_t OFFB = OFFA + 3 * ABUF;        // 50176
    constexpr uint32_t BBUF = NB * 128;

    extern __shared__ char smem[];
    const uint32_t sb = smem_u32(smem);
    float* s_bias = (float*)smem;

    const int bid = blockIdx.x;
    const int n = bid / (MBLK * NBLK);
    const int r = bid - n * (MBLK * NBLK);
    const int mblk = r / NBLK;
    const int nblk = r - mblk * NBLK;
    const int oh0 = mblk * OH_TILE;

    const int tid = threadIdx.x;
    const int warp = tid >> 5;
    const int lane = tid & 31;
    const int mwarp = warp >> 1;
    const int nwarp = warp & 1;

    if (tid < NB) s_bias[tid] = bias[nblk * NB + tid];

    // -------- staging lambdas --------
    const int am = tid >> 1;
    const int a_ohl = am >> LOG_OW;
    const int a_ow = am & (OW - 1);

    auto issueA = [&](int c, uint32_t abase) {
        if (IS_CONV1) {
            const int ihb = (oh0 + a_ohl) * 2;     // padded coords (+kh)
            const int iwb = a_ow * 2;              // (+kw)
#pragma unroll
            for (int i = 0; i < 5; i++) {
                int j = (tid & 1) + 2 * i;
                if (j <= 8) {
                    int kh = j / 3, kw = j - kh * 3;
                    const __half* src =
                        in + (((size_t)n * 130 + ihb + kh) * 130 + iwb + kw) * 4;
                    uint32_t dst = sb + abase + swz((uint32_t)(am * 128 + j * 8));
                    asm volatile("cp.async.ca.shared.global [%0], [%1], 8;"
                                 :: "r"(dst), "l"(src));
                }
            }
        } else {
            const int tap = c / CPT;
            const int ic0 = (c & (CPT - 1)) * 64;
            const int kh = tap / 3, kw = tap - kh * 3;
            const int ih = (oh0 + a_ohl) * 2 - 1 + kh;
            const int iw = a_ow * 2 - 1 + kw;
            const bool valid = ((unsigned)ih < (unsigned)IH) &&
                               ((unsigned)iw < (unsigned)IW);
            const __half* src = valid
                ? in + (((size_t)n * IH + ih) * IW + iw) * ICP + ic0 : in;
            const int sz = valid ? 16 : 0;
#pragma unroll
            for (int i = 0; i < 4; i++) {
                int u = (tid & 1) * 4 + i;
                uint32_t dst = sb + abase + swz((uint32_t)(am * 128 + u * 16));
                asm volatile("cp.async.cg.shared.global [%0], [%1], 16, %2;"
                             :: "r"(dst), "l"(src + u * 8), "r"(sz));
            }
        }
    };
    auto issueB = [&](int c, uint32_t bbase) {
        constexpr int UPT = NB / 32;
#pragma unroll
        for (int i = 0; i < UPT; i++) {
            int u = tid * UPT + i;
            int row = u >> 3, j = u & 7;
            const __half* src = wrep + (size_t)(nblk * NB + row) * KTOT + c * 64 + j * 8;
            uint32_t dst = sb + bbase + swz((uint32_t)(row * 128 + j * 16));
            asm volatile("cp.async.cg.shared.global [%0], [%1], 16;"
                         :: "r"(dst), "l"(src));
        }
    };

    // -------- accumulators + mma --------
    float acc[2][NT][4];
#pragma unroll
    for (int mt = 0; mt < 2; mt++)
#pragma unroll
        for (int nt = 0; nt < NT; nt++)
#pragma unroll
            for (int i = 0; i < 4; i++) acc[mt][nt][i] = 0.f;

    auto do_mma = [&](uint32_t abase, uint32_t bbase) {
#pragma unroll
        for (int ks = 0; ks < 4; ks++) {
            const uint32_t colb = ks * 32 + ((lane >> 4) << 4);
            uint32_t a[2][4], bf[NP][4];
#pragma unroll
            for (int mt = 0; mt < 2; mt++) {
                const uint32_t row = mwarp * 32 + mt * 16 + (lane & 15);
                ldm_x4(a[mt], sb + abase + swz(row * 128 + colb));
            }
#pragma unroll
            for (int np = 0; np < NP; np++) {
                const uint32_t row = nwarp * (NB / 2) + np * 16 + (lane & 15);
                ldm_x4(bf[np], sb + bbase + swz(row * 128 + colb));
            }
#pragma unroll
            for (int mt = 0; mt < 2; mt++)
#pragma unroll
                for (int nt = 0; nt < NT; nt++)
                    mma_f16(acc[mt][nt], a[mt], bf[nt >> 1][nt & 1],
                            bf[nt >> 1][2 + (nt & 1)]);
        }
    };

    // -------- conv1: pre-zero A stage 0 (K padded 36->64) --------
    if (IS_CONV1) {
        uint4 z = make_uint4(0, 0, 0, 0);
#pragma unroll
        for (int i = 0; i < 4; i++)
            *(uint4*)(smem + OFFA + (tid + i * 256) * 16) = z;
        __syncthreads();
    }

    // -------- pipeline: one sync per chunk --------
    issueB(0, OFFB);
    issueA(0, OFFA);
    CP_COMMIT();
    if (NCH > 1) {
        issueB(1, OFFB + BBUF);
        issueA(1, OFFA + ABUF);
        CP_COMMIT();
    }

    int bi = 0;
#pragma unroll 1
    for (int c = 0; c < NCH; c++) {
        if (c + 1 < NCH) { CP_WAIT1(); } else { CP_WAIT0(); }
        __syncthreads();
        do_mma(OFFA + (uint32_t)bi * ABUF, OFFB + (uint32_t)bi * BBUF);
        if (c + 2 < NCH) {
            int b2 = bi + 2; if (b2 >= 3) b2 -= 3;
            issueB(c + 2, OFFB + (uint32_t)b2 * BBUF);
            issueA(c + 2, OFFA + (uint32_t)b2 * ABUF);
            CP_COMMIT();
        }
        if (++bi == 3) bi = 0;
    }
    __syncthreads();   // all warps done with smem before epilogue reuse

    // -------- epilogue --------
    if (!FUSE_POOL) {
        constexpr uint32_t ES = NB * 2 + 16;
        char* epi = smem + OFFA;
#pragma unroll
        for (int mt = 0; mt < 2; mt++) {
            const int r0 = mwarp * 32 + mt * 16 + (lane >> 2);
#pragma unroll
            for (int nt = 0; nt < NT; nt++) {
                const int c0 = nwarp * (NB / 2) + nt * 8 + (lane & 3) * 2;
                const float b0 = s_bias[c0], b1 = s_bias[c0 + 1];
                __half2 v0 = __floats2half2_rn(fmaxf(acc[mt][nt][0] + b0, 0.f),
                                               fmaxf(acc[mt][nt][1] + b1, 0.f));
                __half2 v1 = __floats2half2_rn(fmaxf(acc[mt][nt][2] + b0, 0.f),
                                               fmaxf(acc[mt][nt][3] + b1, 0.f));
                *(__half2*)(epi + r0 * ES + c0 * 2) = v0;
                *(__half2*)(epi + (r0 + 8) * ES + c0 * 2) = v1;
            }
        }
        __syncthreads();
        constexpr int ROWB = NB / 8;          // uint4 per row
        constexpr int T4 = 128 * ROWB / 256;
        __half* outh = (__half*)outp;
#pragma unroll
        for (int i = 0; i < T4; i++) {
            int idx = tid + i * 256;
            int r2 = idx / ROWB;
            int j = idx & (ROWB - 1);
            uint4 v = *(const uint4*)(epi + r2 * ES + j * 16);
            int ohl = r2 >> LOG_OW, ow = r2 & (OW - 1);
            __half* dst = outh + (((size_t)n * OH + oh0 + ohl) * OW + ow) * OCTOT
                        + nblk * NB + j * 8;
            *(uint4*)dst = v;
        }
    } else {
        float* s_red = (float*)(smem + OFFA);   // [NB][4]
#pragma unroll
        for (int nt = 0; nt < NT; nt++) {
            const int c0 = nwarp * (NB / 2) + nt * 8 + (lane & 3) * 2;
            const float b0 = s_bias[c0], b1 = s_bias[c0 + 1];
            float s0 = 0.f, s1 = 0.f;
#pragma unroll
            for (int mt = 0; mt < 2; mt++) {
                s0 += fmaxf(acc[mt][nt][0] + b0, 0.f) + fmaxf(acc[mt][nt][2] + b0, 0.f);
                s1 += fmaxf(acc[mt][nt][1] + b1, 0.f) + fmaxf(acc[mt][nt][3] + b1, 0.f);
            }
#pragma unroll
            for (int off = 16; off >= 4; off >>= 1) {
                s0 += __shfl_xor_sync(0xffffffffu, s0, off);
                s1 += __shfl_xor_sync(0xffffffffu, s1, off);
            }
            if ((lane >> 2) == 0) {
                s_red[c0 * 4 + mwarp] = s0;
                s_red[(c0 + 1) * 4 + mwarp] = s1;
            }
        }
        __syncthreads();
        if (tid < NB) {
            float s = s_red[tid * 4] + s_red[tid * 4 + 1]
                    + s_red[tid * 4 + 2] + s_red[tid * 4 + 3];
            ((float*)outp)[((size_t)n * MBLK + mblk) * 256 + nblk * NB + tid] = s;
        }
    }
}

// ---------------------------------------------------------------------------
// Fused per-sample MLP chain — 512 threads, split-K on every layer.
// ---------------------------------------------------------------------------
__global__ void __launch_bounds__(512)
mlp_chain_kernel(const float* __restrict__ vpart, const float* __restrict__ prop,
                 const int* __restrict__ task_ids,
                 const float* __restrict__ p1_w, const float* __restrict__ p1_b,
                 const float* __restrict__ p2_w, const float* __restrict__ p2_b,
                 const float* __restrict__ f1_w, const float* __restrict__ f1_b,
                 const float* __restrict__ f2_w, const float* __restrict__ f2_b,
                 const float* __restrict__ task_emb,
                 const float* __restrict__ g_w, const float* __restrict__ g_b,
                 const float* __restrict__ h1_w, const float* __restrict__ h1_b,
                 const float* __restrict__ h2_w, const float* __restrict__ h2_b,
                 const float* __restrict__ h3_w, const float* __restrict__ h3_b,
                 float* __restrict__ out)
{
    const int n = blockIdx.x;
    const int tid = threadIdx.x;

    __shared__ float sA[320];
    __shared__ float sB[256];
    __shared__ float sP[512];
    __shared__ float sx[7];
    __shared__ float sh[64];

    if (tid < 256)
        sA[tid] = (vpart[((size_t)n * 2 + 0) * 256 + tid] +
                   vpart[((size_t)n * 2 + 1) * 256 + tid]) * (1.f / 256.f);
    if (tid < 7) sx[tid] = prop[n * 7 + tid];
    const int t = task_ids[n];
    __syncthreads();

    // p1: 7 -> 64, relu
    if (tid < 64) {
        float a = p1_b[tid];
#pragma unroll
        for (int i = 0; i < 7; i++) a += sx[i] * p1_w[i * 64 + tid];
        sh[tid] = fmaxf(a, 0.f);
    }
    __syncthreads();
    // p2: 64 -> 64 (no relu), split-K 2
    if (tid < 128) {
        const int o = tid & 63, kh = tid >> 6, k0 = kh * 32;
        float a0 = 0.f, a1 = 0.f, a2 = 0.f, a3 = 0.f;
#pragma unroll
        for (int i = 0; i < 32; i += 4) {
            int k = k0 + i;
            a0 += sh[k] * p2_w[k * 64 + o];
            a1 += sh[k + 1] * p2_w[(k + 1) * 64 + o];
            a2 += sh[k + 2] * p2_w[(k + 2) * 64 + o];
            a3 += sh[k + 3] * p2_w[(k + 3) * 64 + o];
        }
        sP[tid] = (a0 + a1) + (a2 + a3);
    }
    __syncthreads();
    if (tid < 64) sA[256 + tid] = sP[tid] + sP[tid + 64] + p2_b[tid];
    __syncthreads();

    // f1: 320 -> 256, relu, split-K 2
    {
        const int o = tid & 255, kh = tid >> 8, k0 = kh * 160;
        float a0 = 0.f, a1 = 0.f, a2 = 0.f, a3 = 0.f;
        for (int i = 0; i < 160; i += 4) {
            int k = k0 + i;
            a0 += sA[k] * f1_w[k * 256 + o];
            a1 += sA[k + 1] * f1_w[(k + 1) * 256 + o];
            a2 += sA[k + 2] * f1_w[(k + 2) * 256 + o];
            a3 += sA[k + 3] * f1_w[(k + 3) * 256 + o];
        }
        sP[tid] = (a0 + a1) + (a2 + a3);
    }
    __syncthreads();
    if (tid < 256) sB[tid] = fmaxf(sP[tid] + sP[tid + 256] + f1_b[tid], 0.f);
    __syncthreads();

    // f2: 256 -> 256, relu, split-K 2
    {
        const int o = tid & 255, kh = tid >> 8, k0 = kh * 128;
        float a0 = 0.f, a1 = 0.f, a2 = 0.f, a3 = 0.f;
        for (int i = 0; i < 128; i += 4) {
            int k = k0 + i;
            a0 += sB[k] * f2_w[k * 256 + o];
            a1 += sB[k + 1] * f2_w[(k + 1) * 256 + o];
            a2 += sB[k + 2] * f2_w[(k + 2) * 256 + o];
            a3 += sB[k + 3] * f2_w[(k + 3) * 256 + o];
        }
        sP[tid] = (a0 + a1) + (a2 + a3);
    }
    __syncthreads();
    if (tid < 256) sA[tid] = fmaxf(sP[tid] + sP[tid + 256] + f2_b[tid], 0.f);
    if (tid >= 256 && tid < 288) sA[tid] = task_emb[t * 32 + (tid - 256)];
    __syncthreads();

    // g: 288 -> 256, relu, split-K 2
    {
        const int o = tid & 255, kh = tid >> 8, k0 = kh * 144;
        float a0 = 0.f, a1 = 0.f, a2 = 0.f, a3 = 0.f;
        for (int i = 0; i < 144; i += 4) {
            int k = k0 + i;
            a0 += sA[k] * g_w[k * 256 + o];
            a1 += sA[k + 1] * g_w[(k + 1) * 256 + o];
            a2 += sA[k + 2] * g_w[(k + 2) * 256 + o];
            a3 += sA[k + 3] * g_w[(k + 3) * 256 + o];
        }
        sP[tid] = (a0 + a1) + (a2 + a3);
    }
    __syncthreads();
    if (tid < 256) sB[tid] = fmaxf(sP[tid] + sP[tid + 256] + g_b[tid], 0.f);
    __syncthreads();

    // h1: 256 -> 128, relu, split-K 4
    {
        const float* w1 = h1_w + (size_t)t * ENC_DIM * HEAD_HID;
        const int o = tid & 127, kh = tid >> 7, k0 = kh * 64;
        float a0 = 0.f, a1 = 0.f, a2 = 0.f, a3 = 0.f;
        for (int i = 0; i < 64; i += 4) {
            int k = k0 + i;
            a0 += sB[k] * w1[k * 128 + o];
            a1 += sB[k + 1] * w1[(k + 1) * 128 + o];
            a2 += sB[k + 2] * w1[(k + 2) * 128 + o];
            a3 += sB[k + 3] * w1[(k + 3) * 128 + o];
        }
        sP[tid] = (a0 + a1) + (a2 + a3);
    }
    __syncthreads();
    if (tid < 128)
        sA[tid] = fmaxf(sP[tid] + sP[tid + 128] + sP[tid + 256] + sP[tid + 384]
                        + h1_b[t * 128 + tid], 0.f);
    __syncthreads();

    // h2: 128 -> 128, relu, split-K 4
    {
        const float* w2 = h2_w + (size_t)t * HEAD_HID * HEAD_HID;
        const int o = tid & 127, kh = tid >> 7, k0 = kh * 32;
        float a0 = 0.f, a1 = 0.f, a2 = 0.f, a3 = 0.f;
#pragma unroll
        for (int i = 0; i < 32; i += 4) {
            int k = k0 + i;
            a0 += sA[k] * w2[k * 128 + o];
            a1 += sA[k + 1] * w2[(k + 1) * 128 + o];
            a2 += sA[k + 2] * w2[(k + 2) * 128 + o];
            a3 += sA[k + 3] * w2[(k + 3) * 128 + o];
        }
        sP[tid] = (a0 + a1) + (a2 + a3);
    }
    __syncthreads();
    if (tid < 128)
        sB[tid] = fmaxf(sP[tid] + sP[tid + 128] + sP[tid + 256] + sP[tid + 384]
                        + h2_b[t * 128 + tid], 0.f);
    __syncthreads();

    // h3: 128 -> 4, one warp per output
    if (tid < 128) {
        const float* w3 = h3_w + (size_t)t * HEAD_HID * 4;
        const int o = tid >> 5;
        const int l = tid & 31;
        float a = 0.f;
#pragma unroll
        for (int j = 0; j < 4; j++) a += sB[l + j * 32] * w3[(l + j * 32) * 4 + o];
#pragma unroll
        for (int d = 16; d > 0; d >>= 1) a += __shfl_xor_sync(0xffffffffu, a, d);
        if (l == 0) out[n * 4 + o] = a + h3_b[t * 4 + o];
    }
}

// ---------------------------------------------------------------------------
extern "C" void kernel_launch(void* const* d_in, const int* in_sizes, int n_in,
                              void* d_out, int out_size)
{
    const float* images = (const float*)d_in[0];
    const float* prop   = (const float*)d_in[1];
    const int*   tids   = (const int*)d_in[2];
    const float* c1_w = (const float*)d_in[3];
    const float* c1_b = (const float*)d_in[4];
    const float* c2_w = (const float*)d_in[5];
    const float* c2_b = (const float*)d_in[6];
    const float* c3_w = (const float*)d_in[7];
    const float* c3_b = (const float*)d_in[8];
    const float* p1_w = (const float*)d_in[9];
    const float* p1_b = (const float*)d_in[10];
    const float* p2_w = (const float*)d_in[11];
    const float* p2_b = (const float*)d_in[12];
    const float* f1_w = (const float*)d_in[13];
    const float* f1_b = (const float*)d_in[14];
    const float* f2_w = (const float*)d_in[15];
    const float* f2_b = (const float*)d_in[16];
    const float* temb = (const float*)d_in[17];
    const float* g_w  = (const float*)d_in[18];
    const float* g_b  = (const float*)d_in[19];
    const float* h1_w = (const float*)d_in[20];
    const float* h1_b = (const float*)d_in[21];
    const float* h2_w = (const float*)d_in[22];
    const float* h2_b = (const float*)d_in[23];
    const float* h3_w = (const float*)d_in[24];
    const float* h3_b = (const float*)d_in[25];
    float* out = (float*)d_out;

    __half *imgT, *act1, *act2, *w1r, *w2r, *w3r;
    float* vpart;
    cudaGetSymbolAddress((void**)&imgT, g_imgT);
    cudaGetSymbolAddress((void**)&act1, g_act1);
    cudaGetSymbolAddress((void**)&act2, g_act2);
    cudaGetSymbolAddress((void**)&w1r, g_w1rep);
    cudaGetSymbolAddress((void**)&w2r, g_w2rep);
    cudaGetSymbolAddress((void**)&w3r, g_w3rep);
    cudaGetSymbolAddress((void**)&vpart, g_vpart);

    // repacks
    repack_img<<<(BATCH * 130 * 130 + 511) / 512, 512>>>(images, imgT);
    repack_w_all<<<(4096 + 73728 + 294912 + 255) / 256, 256>>>(
        c1_w, c2_w, c3_w, w1r, w2r, w3r);

    // conv1: imgT -> act1 [256,64,64,64] NHWC half. NB=64, MBLK=32
    {
        constexpr int SM = 50176 + 3 * (64 * 128);
        auto k = conv_cp_kernel<4, 64, 64, 64, 128, 128, 2, false, true>;
        cudaFuncSetAttribute(k, cudaFuncAttributeMaxDynamicSharedMemorySize, SM);
        k<<<BATCH * 32, 256, SM>>>(imgT, w1r, c1_b, act1);
    }
    // conv2: act1 -> act2 [256,32,32,128] NHWC half. NB=128, MBLK=8
    {
        constexpr int SM = 50176 + 3 * (128 * 128);
        auto k = conv_cp_kernel<64, 576, 128, 128, 64, 64, 4, false, false>;
        cudaFuncSetAttribute(k, cudaFuncAttributeMaxDynamicSharedMemorySize, SM);
        k<<<BATCH * 8, 256, SM>>>(act1, w2r, c2_b, act2);
    }
    // conv3 + pool partials -> vpart. NB=128, MBLK=2, NBLK=2
    {
        constexpr int SM = 50176 + 3 * (128 * 128);
        auto k = conv_cp_kernel<128, 1152, 256, 128, 32, 32, 8, true, false>;
        cudaFuncSetAttribute(k, cudaFuncAttributeMaxDynamicSharedMemorySize, SM);
        k<<<BATCH * 2 * 2, 256, SM>>>(act2, w3r, c3_b, vpart);
    }

    mlp_chain_kernel<<<BATCH, 512>>>(
        vpart, prop, tids,
        p1_w, p1_b, p2_w, p2_b,
        f1_w, f1_b, f2_w, f2_b,
        temb, g_w, g_b,
        h1_w, h1_b, h2_w, h2_b, h3_w, h3_b,
        out);
}